// round 7
// baseline (speedup 1.0000x reference)
#include <cuda_runtime.h>
#include <math.h>

#define NN 2048
#define DD 256
#define HH 8
#define DKK 32

// ---------------- scratch (static device globals; no allocation) ----------------
__device__ float g_q[NN * DD];
__device__ float g_k[NN * DD];
__device__ float g_v[NN * DD];
__device__ float g_inv[NN];        // 0.5 / (rowsum + eps)
__device__ float g_yadj[NN * DD];  // 0.5 * p_adj @ V
__device__ float g_x[NN * DD];     // blended pre-output-proj

// ================================================================
// GEMM: C[m,n] = sum_k A[m,k] * B[n,k] + bias[n]
// A: [M,K] row-major, B: [Nn,K] row-major (i.e. A @ B^T), C: [M,256]
// BM=32 BN=64 BK=32, 128 threads, 4x4 micro-tile. K=256.
// ================================================================
__global__ __launch_bounds__(128) void gemm_abt_k256(const float* __restrict__ A,
                              const float* __restrict__ B,
                              const float* __restrict__ bias,
                              float* __restrict__ C) {
    const int K = 256;
    __shared__ float As[32][33];   // [row][k]
    __shared__ float Bs[32][64];   // [k][col]
    int tid = threadIdx.x;
    int tx = tid & 15, ty = tid >> 4;
    int m0 = blockIdx.x * 32;
    int n0 = blockIdx.y * 64;

    // bias for this thread's 4 output columns (hoisted ahead of mainloop)
    float4 bb = *(const float4*)(bias + n0 + tx * 4);

    float acc[4][4] = {};

    for (int k0 = 0; k0 < K; k0 += 32) {
        // load A tile (32x32)
#pragma unroll
        for (int p = 0; p < 2; p++) {
            int idx = p * 512 + tid * 4;
            int ar = idx >> 5, ac = idx & 31;
            float4 a = *(const float4*)(A + (size_t)(m0 + ar) * K + k0 + ac);
            As[ar][ac] = a.x; As[ar][ac + 1] = a.y; As[ar][ac + 2] = a.z; As[ar][ac + 3] = a.w;
        }
        // load B tile (64 rows x 32 k), transposed into Bs[k][col]
#pragma unroll
        for (int p = 0; p < 4; p++) {
            int idx = p * 512 + tid * 4;
            int br = idx >> 5, bc = idx & 31;
            float4 b = *(const float4*)(B + (size_t)(n0 + br) * K + k0 + bc);
            Bs[bc][br] = b.x; Bs[bc + 1][br] = b.y; Bs[bc + 2][br] = b.z; Bs[bc + 3][br] = b.w;
        }
        __syncthreads();
#pragma unroll
        for (int kk = 0; kk < 32; kk++) {
            float4 b = *(const float4*)&Bs[kk][tx * 4];
#pragma unroll
            for (int i = 0; i < 4; i++) {
                float a = As[ty * 4 + i][kk];
                acc[i][0] += a * b.x; acc[i][1] += a * b.y;
                acc[i][2] += a * b.z; acc[i][3] += a * b.w;
            }
        }
        __syncthreads();
    }

    int n = n0 + tx * 4;
#pragma unroll
    for (int i = 0; i < 4; i++) {
        float4 o;
        o.x = acc[i][0] + bb.x; o.y = acc[i][1] + bb.y;
        o.z = acc[i][2] + bb.z; o.w = acc[i][3] + bb.w;
        *(float4*)(C + (size_t)(m0 + ty * 4 + i) * DD + n) = o;
    }
}

// ================================================================
// Adjacency row sums -> g_inv[n] = 0.5 / (sum + 1e-6)
// ================================================================
__global__ __launch_bounds__(256) void rowsum_kernel(const float* __restrict__ adj) {
    int row = blockIdx.x;
    const float4* r = (const float4*)(adj + (size_t)row * NN);
    float s = 0.f;
    for (int i = threadIdx.x; i < NN / 4; i += 256) {
        float4 t = r[i];
        s += t.x + t.y + t.z + t.w;
    }
#pragma unroll
    for (int o = 16; o > 0; o >>= 1) s += __shfl_xor_sync(0xffffffffu, s, o);
    __shared__ float red[8];
    if ((threadIdx.x & 31) == 0) red[threadIdx.x >> 5] = s;
    __syncthreads();
    if (threadIdx.x < 8) {
        float t = red[threadIdx.x];
#pragma unroll
        for (int o = 4; o > 0; o >>= 1) t += __shfl_xor_sync(0xffu, t, o);
        if (threadIdx.x == 0) g_inv[row] = 0.5f / (t + 1e-6f);
    }
}

// ================================================================
// Y[m,n] = g_inv[m] * sum_k adj[m,k] * V[k,n]    (NN GEMM, K=2048)
// Writes g_yadj. BM=32 BN=64 BK=32, 128 threads.
// ================================================================
__global__ __launch_bounds__(128) void gemm_adj(const float* __restrict__ A) {
    const int K = NN;
    __shared__ float As[32][33];
    __shared__ float Bs[32][64];
    int tid = threadIdx.x;
    int tx = tid & 15, ty = tid >> 4;
    int m0 = blockIdx.x * 32;
    int n0 = blockIdx.y * 64;

    float acc[4][4] = {};

    for (int k0 = 0; k0 < K; k0 += 32) {
#pragma unroll
        for (int p = 0; p < 2; p++) {
            int idx = p * 512 + tid * 4;
            int ar = idx >> 5, ac = idx & 31;
            float4 a = *(const float4*)(A + (size_t)(m0 + ar) * K + k0 + ac);
            As[ar][ac] = a.x; As[ar][ac + 1] = a.y; As[ar][ac + 2] = a.z; As[ar][ac + 3] = a.w;
        }
        // V tile: rows k0..k0+31, cols n0..n0+63 (already [k][n] layout)
#pragma unroll
        for (int p = 0; p < 4; p++) {
            int idx = p * 512 + tid * 4;
            int vr = idx >> 6, vc = idx & 63;
            float4 b = *(const float4*)(g_v + (size_t)(k0 + vr) * DD + n0 + vc);
            *(float4*)&Bs[vr][vc] = b;
        }
        __syncthreads();
#pragma unroll
        for (int kk = 0; kk < 32; kk++) {
            float4 b = *(const float4*)&Bs[kk][tx * 4];
#pragma unroll
            for (int i = 0; i < 4; i++) {
                float a = As[ty * 4 + i][kk];
                acc[i][0] += a * b.x; acc[i][1] += a * b.y;
                acc[i][2] += a * b.z; acc[i][3] += a * b.w;
            }
        }
        __syncthreads();
    }

#pragma unroll
    for (int i = 0; i < 4; i++) {
        float rs = g_inv[m0 + ty * 4 + i];
        float4 o;
        o.x = acc[i][0] * rs; o.y = acc[i][1] * rs;
        o.z = acc[i][2] * rs; o.w = acc[i][3] * rs;
        *(float4*)(g_yadj + (size_t)(m0 + ty * 4 + i) * DD + n0 + tx * 4) = o;
    }
}

// ================================================================
// Flash attention per head, online softmax. Each warp owns 2 query rows,
// 16 warps/block => 32 rows/block. grid = (N/32, H).
// Blends: g_x = 0.5 * softmax(QK^T/sqrt(dk)+mask) @ V_h  +  g_yadj
// ================================================================
__global__ __launch_bounds__(512) void attn_kernel(const float* __restrict__ mask) {
    __shared__ float Ks[32][33];
    __shared__ float Vs[32][32];
    int tid = threadIdx.x;
    int warp = tid >> 5, lane = tid & 31;
    int h = blockIdx.y;
    int row0 = blockIdx.x * 32;
    int r0 = row0 + warp * 2;
    int col = h * 32 + lane;

    // q rows into registers via shuffle broadcast
    float qv0 = g_q[(size_t)r0 * DD + col];
    float qv1 = g_q[(size_t)(r0 + 1) * DD + col];
    float q0[32], q1[32];
#pragma unroll
    for (int d = 0; d < 32; d++) {
        q0[d] = __shfl_sync(0xffffffffu, qv0, d);
        q1[d] = __shfl_sync(0xffffffffu, qv1, d);
    }

    float m0 = -INFINITY, m1 = -INFINITY;
    float l0 = 0.f, l1 = 0.f, acc0 = 0.f, acc1 = 0.f;
    const float scale = 0.17677669529663687f;  // 1/sqrt(32)

    int krow = tid >> 4, kc = (tid & 15) * 2;

    // hoisted row base pointers
    const float* mrow0 = mask + (size_t)r0 * NN + lane;
    const float* mrow1 = mask + (size_t)(r0 + 1) * NN + lane;
    const float* kbase = g_k + (size_t)krow * DD + h * 32 + kc;
    const float* vbase = g_v + (size_t)krow * DD + h * 32 + kc;

    for (int k0 = 0; k0 < NN; k0 += 32) {
        __syncthreads();
        float2 kv = *(const float2*)(kbase + (size_t)k0 * DD);
        Ks[krow][kc] = kv.x; Ks[krow][kc + 1] = kv.y;
        float2 vv = *(const float2*)(vbase + (size_t)k0 * DD);
        Vs[krow][kc] = vv.x; Vs[krow][kc + 1] = vv.y;
        __syncthreads();

        // lane j computes score against key (k0 + j) for both rows
        float s0 = 0.f, s1 = 0.f;
#pragma unroll
        for (int d = 0; d < 32; d++) {
            float kd = Ks[lane][d];
            s0 += q0[d] * kd;
            s1 += q1[d] * kd;
        }
        s0 = s0 * scale + mrow0[k0];
        s1 = s1 * scale + mrow1[k0];

        float t0 = s0, t1 = s1;
#pragma unroll
        for (int o = 16; o > 0; o >>= 1) {
            t0 = fmaxf(t0, __shfl_xor_sync(0xffffffffu, t0, o));
            t1 = fmaxf(t1, __shfl_xor_sync(0xffffffffu, t1, o));
        }
        float mn0 = fmaxf(m0, t0), mn1 = fmaxf(m1, t1);
        float p0 = __expf(s0 - mn0), p1 = __expf(s1 - mn1);
        float ps0 = p0, ps1 = p1;
#pragma unroll
        for (int o = 16; o > 0; o >>= 1) {
            ps0 += __shfl_xor_sync(0xffffffffu, ps0, o);
            ps1 += __shfl_xor_sync(0xffffffffu, ps1, o);
        }
        float a0 = __expf(m0 - mn0), a1 = __expf(m1 - mn1);
        l0 = l0 * a0 + ps0;
        l1 = l1 * a1 + ps1;
        acc0 *= a0; acc1 *= a1;
#pragma unroll
        for (int j = 0; j < 32; j++) {
            float vj = Vs[j][lane];
            acc0 += __shfl_sync(0xffffffffu, p0, j) * vj;
            acc1 += __shfl_sync(0xffffffffu, p1, j) * vj;
        }
        m0 = mn0; m1 = mn1;
    }

    g_x[(size_t)r0 * DD + col]       = 0.5f * (acc0 / l0) + g_yadj[(size_t)r0 * DD + col];
    g_x[(size_t)(r0 + 1) * DD + col] = 0.5f * (acc1 / l1) + g_yadj[(size_t)(r0 + 1) * DD + col];
}

// ================================================================
extern "C" void kernel_launch(void* const* d_in, const int* in_sizes, int n_in,
                              void* d_out, int out_size) {
    const float* query = (const float*)d_in[0];
    const float* key   = (const float*)d_in[1];
    const float* value = (const float*)d_in[2];
    const float* mask  = (const float*)d_in[3];
    const float* adj   = (const float*)d_in[4];
    const float* Wq = (const float*)d_in[5];  const float* bq = (const float*)d_in[6];
    const float* Wk = (const float*)d_in[7];  const float* bk = (const float*)d_in[8];
    const float* Wv = (const float*)d_in[9];  const float* bv = (const float*)d_in[10];
    const float* Wo = (const float*)d_in[11]; const float* bo = (const float*)d_in[12];
    float* out = (float*)d_out;

    float *pq, *pk, *pv, *px;
    cudaGetSymbolAddress((void**)&pq, g_q);
    cudaGetSymbolAddress((void**)&pk, g_k);
    cudaGetSymbolAddress((void**)&pv, g_v);
    cudaGetSymbolAddress((void**)&px, g_x);

    dim3 ggrid(NN / 32, DD / 64);

    // QKV projections
    gemm_abt_k256<<<ggrid, 128>>>(query, Wq, bq, pq);
    gemm_abt_k256<<<ggrid, 128>>>(key,   Wk, bk, pk);
    gemm_abt_k256<<<ggrid, 128>>>(value, Wv, bv, pv);

    // adjacency row-normalization factors (with 0.5 lambda folded in)
    rowsum_kernel<<<NN, 256>>>(adj);

    // 0.5 * p_adj @ V
    gemm_adj<<<ggrid, 128>>>(adj);

    // attention + blend -> g_x
    attn_kernel<<<dim3(NN / 32, HH), 512>>>(mask);

    // output projection
    gemm_abt_k256<<<ggrid, 128>>>(px, Wo, bo, out);
}

// round 10
// speedup vs baseline: 1.0079x; 1.0079x over previous
#include <cuda_runtime.h>
#include <cuda_bf16.h>
#include <math.h>
#include <stdint.h>

#define NN 2048
#define DD 256
#define HH 8
#define DKK 32

// ---------------- scratch (static device globals; no allocation) ----------------
__device__ float g_q[NN * DD];
__device__ float g_k[NN * DD];
__device__ float g_v[NN * DD];
__device__ float g_inv[NN];        // 0.5 / (rowsum + eps)
__device__ float g_yadj[NN * DD];  // 0.5 * p_adj @ V
__device__ float g_x[NN * DD];     // blended pre-output-proj
__device__ __nv_bfloat16 g_vt_hi[DD * NN];   // V^T hi  [n][k]
__device__ __nv_bfloat16 g_vt_lo[DD * NN];   // V^T lo  [n][k]
__device__ __nv_bfloat16 g_adj_hi[NN * NN];  // adj hi  [m][k]
__device__ __nv_bfloat16 g_adj_lo[NN * NN];  // adj lo  [m][k]

// ---------------- helpers ----------------
__device__ __forceinline__ uint32_t smem_u32(const void* p) {
    uint32_t a;
    asm("{ .reg .u64 t; cvta.to.shared.u64 t, %1; cvt.u32.u64 %0, t; }" : "=r"(a) : "l"(p));
    return a;
}
__device__ __forceinline__ uint32_t bfpack(__nv_bfloat16 a, __nv_bfloat16 b) {
    return (uint32_t)__bfloat16_as_ushort(a) | ((uint32_t)__bfloat16_as_ushort(b) << 16);
}

// warp-level bf16 MMA m16n8k16 (arch-generic HMMA; tcgen05 is compute_103a-gated
// and this bench compiles PTX for plain compute_103)
#define MMA_BF16(d, a, b0, b1)                                                  \
    asm volatile("mma.sync.aligned.m16n8k16.row.col.f32.bf16.bf16.f32 "        \
        "{%0,%1,%2,%3}, {%4,%5,%6,%7}, {%8,%9}, {%0,%1,%2,%3};"                \
        : "+f"((d)[0]), "+f"((d)[1]), "+f"((d)[2]), "+f"((d)[3])               \
        : "r"((a)[0]), "r"((a)[1]), "r"((a)[2]), "r"((a)[3]), "r"(b0), "r"(b1))

#define LDSM4(r, addr)                                                          \
    asm volatile("ldmatrix.sync.aligned.m8n8.x4.shared.b16 {%0,%1,%2,%3}, [%4];" \
        : "=r"((r)[0]), "=r"((r)[1]), "=r"((r)[2]), "=r"((r)[3]) : "r"(addr))

// ================================================================
// GEMM: C[m,n] = sum_k A[m,k] * B[n,k] + bias[n]   (fp32 SIMT)
// ================================================================
__global__ __launch_bounds__(128) void gemm_abt_k256(const float* __restrict__ A,
                              const float* __restrict__ B,
                              const float* __restrict__ bias,
                              float* __restrict__ C) {
    const int K = 256;
    __shared__ float As[32][33];
    __shared__ float Bs[32][64];
    int tid = threadIdx.x;
    int tx = tid & 15, ty = tid >> 4;
    int m0 = blockIdx.x * 32;
    int n0 = blockIdx.y * 64;

    float4 bb = *(const float4*)(bias + n0 + tx * 4);
    float acc[4][4] = {};

    for (int k0 = 0; k0 < K; k0 += 32) {
#pragma unroll
        for (int p = 0; p < 2; p++) {
            int idx = p * 512 + tid * 4;
            int ar = idx >> 5, ac = idx & 31;
            float4 a = *(const float4*)(A + (size_t)(m0 + ar) * K + k0 + ac);
            As[ar][ac] = a.x; As[ar][ac + 1] = a.y; As[ar][ac + 2] = a.z; As[ar][ac + 3] = a.w;
        }
#pragma unroll
        for (int p = 0; p < 4; p++) {
            int idx = p * 512 + tid * 4;
            int br = idx >> 5, bc = idx & 31;
            float4 b = *(const float4*)(B + (size_t)(n0 + br) * K + k0 + bc);
            Bs[bc][br] = b.x; Bs[bc + 1][br] = b.y; Bs[bc + 2][br] = b.z; Bs[bc + 3][br] = b.w;
        }
        __syncthreads();
#pragma unroll
        for (int kk = 0; kk < 32; kk++) {
            float4 b = *(const float4*)&Bs[kk][tx * 4];
#pragma unroll
            for (int i = 0; i < 4; i++) {
                float a = As[ty * 4 + i][kk];
                acc[i][0] += a * b.x; acc[i][1] += a * b.y;
                acc[i][2] += a * b.z; acc[i][3] += a * b.w;
            }
        }
        __syncthreads();
    }

    int n = n0 + tx * 4;
#pragma unroll
    for (int i = 0; i < 4; i++) {
        float4 o;
        o.x = acc[i][0] + bb.x; o.y = acc[i][1] + bb.y;
        o.z = acc[i][2] + bb.z; o.w = acc[i][3] + bb.w;
        *(float4*)(C + (size_t)(m0 + ty * 4 + i) * DD + n) = o;
    }
}

// ================================================================
// Adjacency pass: row sums -> g_inv, plus fp32 -> bf16 hi/lo split planes
// ================================================================
__global__ __launch_bounds__(256) void rowsum_split_kernel(const float* __restrict__ adj) {
    int row = blockIdx.x;
    const float4* r4 = (const float4*)(adj + (size_t)row * NN);
    __nv_bfloat16* hi = g_adj_hi + (size_t)row * NN;
    __nv_bfloat16* lo = g_adj_lo + (size_t)row * NN;
    float s = 0.f;
    for (int i = threadIdx.x; i < NN / 4; i += 256) {
        float4 t = r4[i];
        s += t.x + t.y + t.z + t.w;
        __nv_bfloat16 hx = __float2bfloat16(t.x);
        __nv_bfloat16 hy = __float2bfloat16(t.y);
        __nv_bfloat16 hz = __float2bfloat16(t.z);
        __nv_bfloat16 hw = __float2bfloat16(t.w);
        *(uint2*)(hi + i * 4) = make_uint2(bfpack(hx, hy), bfpack(hz, hw));
        *(uint2*)(lo + i * 4) = make_uint2(
            bfpack(__float2bfloat16(t.x - __bfloat162float(hx)),
                   __float2bfloat16(t.y - __bfloat162float(hy))),
            bfpack(__float2bfloat16(t.z - __bfloat162float(hz)),
                   __float2bfloat16(t.w - __bfloat162float(hw))));
    }
#pragma unroll
    for (int o = 16; o > 0; o >>= 1) s += __shfl_xor_sync(0xffffffffu, s, o);
    __shared__ float red[8];
    if ((threadIdx.x & 31) == 0) red[threadIdx.x >> 5] = s;
    __syncthreads();
    if (threadIdx.x < 8) {
        float t = red[threadIdx.x];
#pragma unroll
        for (int o = 4; o > 0; o >>= 1) t += __shfl_xor_sync(0xffu, t, o);
        if (threadIdx.x == 0) g_inv[row] = 0.5f / (t + 1e-6f);
    }
}

// ================================================================
// V^T split-convert: g_v [k][n] fp32 -> g_vt_hi/lo [n][k] bf16
// grid (NN/32, DD/32), block (32,8)
// ================================================================
__global__ __launch_bounds__(256) void vt_convert() {
    __shared__ float t[32][33];
    int k0 = blockIdx.x * 32, n0 = blockIdx.y * 32;
    int tx = threadIdx.x, ty = threadIdx.y;
#pragma unroll
    for (int r = 0; r < 4; r++) {
        int k = ty + r * 8;
        t[k][tx] = g_v[(size_t)(k0 + k) * DD + n0 + tx];
    }
    __syncthreads();
#pragma unroll
    for (int r = 0; r < 4; r++) {
        int n = ty + r * 8;
        float v = t[tx][n];
        __nv_bfloat16 h = __float2bfloat16(v);
        g_vt_hi[(size_t)(n0 + n) * NN + k0 + tx] = h;
        g_vt_lo[(size_t)(n0 + n) * NN + k0 + tx] = __float2bfloat16(v - __bfloat162float(h));
    }
}

// ================================================================
// Tensor-core adjacency GEMM via mma.sync (bf16 hi/lo, fp32 accum):
// g_yadj[m,n] = g_inv[m] * sum_k adj[m,k] * V[k,n]
// CTA tile 64x64, BK=32, 256 threads / 8 warps, warp tile 32x16.
// grid (32, 4).
// ================================================================
__global__ __launch_bounds__(256) void gemm_adj_mma() {
    __shared__ __nv_bfloat16 Ahi[64][40];
    __shared__ __nv_bfloat16 Alo[64][40];
    __shared__ __nv_bfloat16 Bhi[64][40];
    __shared__ __nv_bfloat16 Blo[64][40];

    int tid = threadIdx.x;
    int wid = tid >> 5, lane = tid & 31;
    int m0 = blockIdx.x * 64, n0 = blockIdx.y * 64;
    int wm = (wid >> 2) * 32;     // warp row offset in CTA tile (0/32)
    int wn = (wid & 3) * 16;      // warp col offset (0/16/32/48)

    // ldmatrix lane -> (row, col-elem) offsets
    int a_m = lane & 15, a_k = (lane >> 4) << 3;                 // A x4: M0..M3
    int b_n = (lane & 7) + ((lane >> 4) << 3);                   // B x4: t0b0,t0b1,t1b0,t1b1
    int b_k = ((lane >> 3) & 1) << 3;

    // smem load coords (one int4 = 8 bf16 per thread per plane)
    int lr = tid >> 2, lc = (tid & 3) * 8;

    float acc[2][2][4] = {};

    for (int kb = 0; kb < NN / 32; kb++) {
        int k0 = kb * 32;
        *(int4*)&Ahi[lr][lc] = *(const int4*)(g_adj_hi + (size_t)(m0 + lr) * NN + k0 + lc);
        *(int4*)&Alo[lr][lc] = *(const int4*)(g_adj_lo + (size_t)(m0 + lr) * NN + k0 + lc);
        *(int4*)&Bhi[lr][lc] = *(const int4*)(g_vt_hi + (size_t)(n0 + lr) * NN + k0 + lc);
        *(int4*)&Blo[lr][lc] = *(const int4*)(g_vt_lo + (size_t)(n0 + lr) * NN + k0 + lc);
        __syncthreads();

#pragma unroll
        for (int ks = 0; ks < 2; ks++) {
            int kk = ks * 16;
            uint32_t ahi[2][4], alo[2][4], bhi[4], blo[4];
#pragma unroll
            for (int mt = 0; mt < 2; mt++) {
                LDSM4(ahi[mt], smem_u32(&Ahi[wm + mt * 16 + a_m][kk + a_k]));
                LDSM4(alo[mt], smem_u32(&Alo[wm + mt * 16 + a_m][kk + a_k]));
            }
            LDSM4(bhi, smem_u32(&Bhi[wn + b_n][kk + b_k]));
            LDSM4(blo, smem_u32(&Blo[wn + b_n][kk + b_k]));

#pragma unroll
            for (int mt = 0; mt < 2; mt++)
#pragma unroll
                for (int nt = 0; nt < 2; nt++) {
                    MMA_BF16(acc[mt][nt], ahi[mt], bhi[nt * 2], bhi[nt * 2 + 1]);
                    MMA_BF16(acc[mt][nt], alo[mt], bhi[nt * 2], bhi[nt * 2 + 1]);
                    MMA_BF16(acc[mt][nt], ahi[mt], blo[nt * 2], blo[nt * 2 + 1]);
                }
        }
        __syncthreads();
    }

    // epilogue: scale by g_inv[m], write g_yadj
    int rbase = wm + (lane >> 2);
    int cbase = wn + 2 * (lane & 3);
#pragma unroll
    for (int mt = 0; mt < 2; mt++) {
        int r = m0 + rbase + mt * 16;
        float rs0 = g_inv[r], rs1 = g_inv[r + 8];
#pragma unroll
        for (int nt = 0; nt < 2; nt++) {
            int c = n0 + cbase + nt * 8;
            float2 o0 = make_float2(acc[mt][nt][0] * rs0, acc[mt][nt][1] * rs0);
            float2 o1 = make_float2(acc[mt][nt][2] * rs1, acc[mt][nt][3] * rs1);
            *(float2*)(g_yadj + (size_t)r * DD + c) = o0;
            *(float2*)(g_yadj + (size_t)(r + 8) * DD + c) = o1;
        }
    }
}

// ================================================================
// Flash attention per head, online softmax (fp32 SIMT, unchanged)
// ================================================================
__global__ __launch_bounds__(512) void attn_kernel(const float* __restrict__ mask) {
    __shared__ float Ks[32][33];
    __shared__ float Vs[32][32];
    int tid = threadIdx.x;
    int warp = tid >> 5, lane = tid & 31;
    int h = blockIdx.y;
    int row0 = blockIdx.x * 32;
    int r0 = row0 + warp * 2;
    int col = h * 32 + lane;

    float qv0 = g_q[(size_t)r0 * DD + col];
    float qv1 = g_q[(size_t)(r0 + 1) * DD + col];
    float q0[32], q1[32];
#pragma unroll
    for (int d = 0; d < 32; d++) {
        q0[d] = __shfl_sync(0xffffffffu, qv0, d);
        q1[d] = __shfl_sync(0xffffffffu, qv1, d);
    }

    float m0 = -INFINITY, m1 = -INFINITY;
    float l0 = 0.f, l1 = 0.f, acc0 = 0.f, acc1 = 0.f;
    const float scale = 0.17677669529663687f;

    int krow = tid >> 4, kc = (tid & 15) * 2;
    const float* mrow0 = mask + (size_t)r0 * NN + lane;
    const float* mrow1 = mask + (size_t)(r0 + 1) * NN + lane;
    const float* kbase = g_k + (size_t)krow * DD + h * 32 + kc;
    const float* vbase = g_v + (size_t)krow * DD + h * 32 + kc;

    for (int k0 = 0; k0 < NN; k0 += 32) {
        __syncthreads();
        float2 kv = *(const float2*)(kbase + (size_t)k0 * DD);
        Ks[krow][kc] = kv.x; Ks[krow][kc + 1] = kv.y;
        float2 vv = *(const float2*)(vbase + (size_t)k0 * DD);
        Vs[krow][kc] = vv.x; Vs[krow][kc + 1] = vv.y;
        __syncthreads();

        float s0 = 0.f, s1 = 0.f;
#pragma unroll
        for (int d = 0; d < 32; d++) {
            float kd = Ks[lane][d];
            s0 += q0[d] * kd;
            s1 += q1[d] * kd;
        }
        s0 = s0 * scale + mrow0[k0];
        s1 = s1 * scale + mrow1[k0];

        float t0 = s0, t1 = s1;
#pragma unroll
        for (int o = 16; o > 0; o >>= 1) {
            t0 = fmaxf(t0, __shfl_xor_sync(0xffffffffu, t0, o));
            t1 = fmaxf(t1, __shfl_xor_sync(0xffffffffu, t1, o));
        }
        float mn0 = fmaxf(m0, t0), mn1 = fmaxf(m1, t1);
        float p0 = __expf(s0 - mn0), p1 = __expf(s1 - mn1);
        float ps0 = p0, ps1 = p1;
#pragma unroll
        for (int o = 16; o > 0; o >>= 1) {
            ps0 += __shfl_xor_sync(0xffffffffu, ps0, o);
            ps1 += __shfl_xor_sync(0xffffffffu, ps1, o);
        }
        float a0 = __expf(m0 - mn0), a1 = __expf(m1 - mn1);
        l0 = l0 * a0 + ps0;
        l1 = l1 * a1 + ps1;
        acc0 *= a0; acc1 *= a1;
#pragma unroll
        for (int j = 0; j < 32; j++) {
            float vj = Vs[j][lane];
            acc0 += __shfl_sync(0xffffffffu, p0, j) * vj;
            acc1 += __shfl_sync(0xffffffffu, p1, j) * vj;
        }
        m0 = mn0; m1 = mn1;
    }

    g_x[(size_t)r0 * DD + col]       = 0.5f * (acc0 / l0) + g_yadj[(size_t)r0 * DD + col];
    g_x[(size_t)(r0 + 1) * DD + col] = 0.5f * (acc1 / l1) + g_yadj[(size_t)(r0 + 1) * DD + col];
}

// ================================================================
extern "C" void kernel_launch(void* const* d_in, const int* in_sizes, int n_in,
                              void* d_out, int out_size) {
    const float* query = (const float*)d_in[0];
    const float* key   = (const float*)d_in[1];
    const float* value = (const float*)d_in[2];
    const float* mask  = (const float*)d_in[3];
    const float* adj   = (const float*)d_in[4];
    const float* Wq = (const float*)d_in[5];  const float* bq = (const float*)d_in[6];
    const float* Wk = (const float*)d_in[7];  const float* bk = (const float*)d_in[8];
    const float* Wv = (const float*)d_in[9];  const float* bv = (const float*)d_in[10];
    const float* Wo = (const float*)d_in[11]; const float* bo = (const float*)d_in[12];
    float* out = (float*)d_out;

    float *pq, *pk, *pv, *px;
    cudaGetSymbolAddress((void**)&pq, g_q);
    cudaGetSymbolAddress((void**)&pk, g_k);
    cudaGetSymbolAddress((void**)&pv, g_v);
    cudaGetSymbolAddress((void**)&px, g_x);

    dim3 ggrid(NN / 32, DD / 64);

    // QKV projections (fp32 SIMT)
    gemm_abt_k256<<<ggrid, 128>>>(query, Wq, bq, pq);
    gemm_abt_k256<<<ggrid, 128>>>(key,   Wk, bk, pk);
    gemm_abt_k256<<<ggrid, 128>>>(value, Wv, bv, pv);

    // V^T bf16 hi/lo for MMA B operand
    vt_convert<<<dim3(NN / 32, DD / 32), dim3(32, 8)>>>();

    // adjacency: row sums + bf16 hi/lo planes
    rowsum_split_kernel<<<NN, 256>>>(adj);

    // 0.5 * p_adj @ V on tensor cores (mma.sync bf16 hi/lo)
    gemm_adj_mma<<<dim3(NN / 64, DD / 64), 256>>>();

    // attention + blend -> g_x
    attn_kernel<<<dim3(NN / 32, HH), 512>>>(mask);

    // output projection
    gemm_abt_k256<<<ggrid, 128>>>(px, Wo, bo, out);
}

// round 13
// speedup vs baseline: 3.0148x; 2.9912x over previous
#include <cuda_runtime.h>
#include <cuda_fp16.h>
#include <math.h>
#include <stdint.h>

#define NN 2048
#define DD 256
#define HH 8

// ---------------- scratch (static device globals; no allocation) ----------------
__device__ float g_inv[NN];                 // 0.5 / (rowsum + eps)
__device__ float g_x[NN * DD];              // 0.5*attn (+ 0.5*p_adj@V accumulated)
__device__ __half g_qh_h[NN * DD];          // Q * (log2e/sqrt(32)), f16 hi
__device__ __half g_qh_l[NN * DD];          //   f16 lo
__device__ __half g_kh_h[NN * DD];          // K f16 hi/lo
__device__ __half g_kh_l[NN * DD];
__device__ __half g_vt_h[DD * NN];          // V^T [d][n] f16 hi/lo
__device__ __half g_vt_l[DD * NN];
__device__ __half g_adj_h[NN * NN];         // adj f16 hi/lo [m][k]
__device__ __half g_adj_l[NN * NN];

#define LOG2E 1.4426950408889634f
#define QSCALE 0.25508218912f   /* log2e / sqrt(32) */

// ---------------- helpers ----------------
__device__ __forceinline__ uint32_t smem_u32(const void* p) {
    uint32_t a;
    asm("{ .reg .u64 t; cvta.to.shared.u64 t, %1; cvt.u32.u64 %0, t; }" : "=r"(a) : "l"(p));
    return a;
}
__device__ __forceinline__ uint32_t hpack(__half a, __half b) {
    return (uint32_t)__half_as_ushort(a) | ((uint32_t)__half_as_ushort(b) << 16);
}

#define MMA_F16(d, a, b0, b1)                                                   \
    asm volatile("mma.sync.aligned.m16n8k16.row.col.f32.f16.f16.f32 "          \
        "{%0,%1,%2,%3}, {%4,%5,%6,%7}, {%8,%9}, {%0,%1,%2,%3};"                \
        : "+f"((d)[0]), "+f"((d)[1]), "+f"((d)[2]), "+f"((d)[3])               \
        : "r"((a)[0]), "r"((a)[1]), "r"((a)[2]), "r"((a)[3]), "r"(b0), "r"(b1))

#define LDSM4(r, ptr)                                                           \
    asm volatile("ldmatrix.sync.aligned.m8n8.x4.shared.b16 {%0,%1,%2,%3}, [%4];" \
        : "=r"((r)[0]), "=r"((r)[1]), "=r"((r)[2]), "=r"((r)[3]) : "r"(smem_u32(ptr)))

// d = {hi: a, lo: b}  (first source -> upper half)
#define CVT_F16X2(d, a, b) \
    asm("cvt.rn.f16x2.f32 %0, %1, %2;" : "=r"(d) : "f"(a), "f"(b))
#define EX2_F16X2(d) \
    asm("ex2.approx.f16x2 %0, %0;" : "+r"(d))

// ================================================================
// Projection GEMM: C = A @ W^T + b  (fp32 SIMT, K=256), epilogue by mode:
//   0: q -> f16 hi/lo, scaled by QSCALE
//   1: k -> f16 hi/lo
//   2: v -> transposed f16 hi/lo into g_vt [d][n]
//   3: f32 out with bias -> Cout
// ================================================================
__global__ __launch_bounds__(128) void gemm_proj(const float* __restrict__ A,
                                                 const float* __restrict__ W,
                                                 const float* __restrict__ bias,
                                                 float* __restrict__ Cout,
                                                 int mode) {
    const int K = 256;
    __shared__ __align__(16) float As[32][33];
    __shared__ __align__(16) float Bs[32][64];
    __shared__ __align__(16) float stage[64][33];   // mode 2 transpose
    int tid = threadIdx.x;
    int tx = tid & 15, ty = tid >> 4;
    int m0 = blockIdx.x * 32;
    int n0 = blockIdx.y * 64;

    float4 bb = *(const float4*)(bias + n0 + tx * 4);
    float acc[4][4] = {};

    for (int k0 = 0; k0 < K; k0 += 32) {
#pragma unroll
        for (int p = 0; p < 2; p++) {
            int idx = p * 512 + tid * 4;
            int ar = idx >> 5, ac = idx & 31;
            float4 a = *(const float4*)(A + (size_t)(m0 + ar) * K + k0 + ac);
            As[ar][ac] = a.x; As[ar][ac + 1] = a.y; As[ar][ac + 2] = a.z; As[ar][ac + 3] = a.w;
        }
#pragma unroll
        for (int p = 0; p < 4; p++) {
            int idx = p * 512 + tid * 4;
            int br = idx >> 5, bc = idx & 31;
            float4 b = *(const float4*)(W + (size_t)(n0 + br) * K + k0 + bc);
            Bs[bc][br] = b.x; Bs[bc + 1][br] = b.y; Bs[bc + 2][br] = b.z; Bs[bc + 3][br] = b.w;
        }
        __syncthreads();
#pragma unroll
        for (int kk = 0; kk < 32; kk++) {
            float4 b = *(const float4*)&Bs[kk][tx * 4];
#pragma unroll
            for (int i = 0; i < 4; i++) {
                float a = As[ty * 4 + i][kk];
                acc[i][0] += a * b.x; acc[i][1] += a * b.y;
                acc[i][2] += a * b.z; acc[i][3] += a * b.w;
            }
        }
        __syncthreads();
    }

    // add bias
#pragma unroll
    for (int i = 0; i < 4; i++) {
        acc[i][0] += bb.x; acc[i][1] += bb.y; acc[i][2] += bb.z; acc[i][3] += bb.w;
    }

    if (mode == 3) {
        int n = n0 + tx * 4;
#pragma unroll
        for (int i = 0; i < 4; i++)
            *(float4*)(Cout + (size_t)(m0 + ty * 4 + i) * DD + n) =
                make_float4(acc[i][0], acc[i][1], acc[i][2], acc[i][3]);
        return;
    }

    if (mode == 2) {
        // transpose-stage then write g_vt hi/lo [d][n]
        __syncthreads();
#pragma unroll
        for (int i = 0; i < 4; i++)
#pragma unroll
            for (int j = 0; j < 4; j++)
                stage[tx * 4 + j][ty * 4 + i] = acc[i][j];
        __syncthreads();
        int d = tid >> 1, half = tid & 1;
        __half hbuf[16], lbuf[16];
#pragma unroll
        for (int e = 0; e < 16; e++) {
            float v = stage[d][half * 16 + e];
            __half hv = __float2half(v);
            hbuf[e] = hv;
            lbuf[e] = __float2half(v - __half2float(hv));
        }
        size_t off = (size_t)(n0 + d) * NN + m0 + half * 16;
#pragma unroll
        for (int c = 0; c < 2; c++) {
            int4 ph, pl;
            ph.x = hpack(hbuf[c*8+0], hbuf[c*8+1]); ph.y = hpack(hbuf[c*8+2], hbuf[c*8+3]);
            ph.z = hpack(hbuf[c*8+4], hbuf[c*8+5]); ph.w = hpack(hbuf[c*8+6], hbuf[c*8+7]);
            pl.x = hpack(lbuf[c*8+0], lbuf[c*8+1]); pl.y = hpack(lbuf[c*8+2], lbuf[c*8+3]);
            pl.z = hpack(lbuf[c*8+4], lbuf[c*8+5]); pl.w = hpack(lbuf[c*8+6], lbuf[c*8+7]);
            *(int4*)(g_vt_h + off + c * 8) = ph;
            *(int4*)(g_vt_l + off + c * 8) = pl;
        }
        return;
    }

    // mode 0/1: row-major f16 hi/lo
    float s = (mode == 0) ? QSCALE : 1.0f;
    __half* Hh = (mode == 0) ? g_qh_h : g_kh_h;
    __half* Hl = (mode == 0) ? g_qh_l : g_kh_l;
    int n = n0 + tx * 4;
#pragma unroll
    for (int i = 0; i < 4; i++) {
        size_t off = (size_t)(m0 + ty * 4 + i) * DD + n;
        __half h[4], l[4];
#pragma unroll
        for (int j = 0; j < 4; j++) {
            float v = acc[i][j] * s;
            h[j] = __float2half(v);
            l[j] = __float2half(v - __half2float(h[j]));
        }
        *(uint2*)(Hh + off) = make_uint2(hpack(h[0], h[1]), hpack(h[2], h[3]));
        *(uint2*)(Hl + off) = make_uint2(hpack(l[0], l[1]), hpack(l[2], l[3]));
    }
}

// ================================================================
// Flash attention via mma.sync. CTA = (128 rows, 1 head), 256 thr / 8 warps.
// Warp w: Q rows 16w..16w+15. Key tiles of 64. No max-subtraction softmax
// (scores ~N(0,1), bounded); l via ones-row in V^T. Writes g_x = 0.5*attn.
// ================================================================
__global__ __launch_bounds__(256) void attn_mma(const float* __restrict__ mask) {
    __shared__ __align__(16) __half Qh[128][40], Ql[128][40];
    __shared__ __align__(16) __half Kh[64][40],  Kl[64][40];
    __shared__ __align__(16) __half Vh[48][72],  Vl[48][72];

    int tid = threadIdx.x;
    int warp = tid >> 5, lane = tid & 31;
    int h = blockIdx.y;
    int r0 = blockIdx.x * 128;

    // Q tile (128 x 32) hi/lo
    for (int i = tid; i < 128 * 4; i += 256) {
        int row = i >> 2, seg = i & 3;
        *(int4*)&Qh[row][seg * 8] = *(const int4*)(g_qh_h + (size_t)(r0 + row) * DD + h * 32 + seg * 8);
        *(int4*)&Ql[row][seg * 8] = *(const int4*)(g_qh_l + (size_t)(r0 + row) * DD + h * 32 + seg * 8);
    }
    // V static rows 32..47: row 32 = ones (l accumulator), rest zero
    for (int i = tid; i < 16 * 72; i += 256) {
        int r = 32 + i / 72, c = i % 72;
        Vh[r][c] = (r == 32) ? __float2half(1.0f) : __ushort_as_half(0);
        Vl[r][c] = __ushort_as_half(0);
    }
    __syncthreads();

    // preload Q fragments (A operand): 2 k-steps
    uint32_t qf_h[2][4], qf_l[2][4];
    int a_m = lane & 15, a_k = (lane >> 4) << 3;
#pragma unroll
    for (int ks = 0; ks < 2; ks++) {
        LDSM4(qf_h[ks], &Qh[warp * 16 + a_m][ks * 16 + a_k]);
        LDSM4(qf_l[ks], &Ql[warp * 16 + a_m][ks * 16 + a_k]);
    }

    int b_n = (lane & 7) + ((lane >> 4) << 3);
    int b_k = ((lane >> 3) & 1) << 3;
    int mrow = r0 + warp * 16 + (lane >> 2);
    int mcol = 2 * (lane & 3);

    float o[5][4] = {};

    for (int kt = 0; kt < 32; kt++) {
        int k0 = kt * 64;
        __syncthreads();
        {   // K tile: 64 rows x 32 halfs, hi/lo
            int row = tid >> 2, seg = tid & 3;
            *(int4*)&Kh[row][seg * 8] = *(const int4*)(g_kh_h + (size_t)(k0 + row) * DD + h * 32 + seg * 8);
            *(int4*)&Kl[row][seg * 8] = *(const int4*)(g_kh_l + (size_t)(k0 + row) * DD + h * 32 + seg * 8);
        }
        {   // V^T tile: 32 d-rows x 64 keys, hi/lo
            int row = tid >> 3, seg = tid & 7;
            *(int4*)&Vh[row][seg * 8] = *(const int4*)(g_vt_h + (size_t)(h * 32 + row) * NN + k0 + seg * 8);
            *(int4*)&Vl[row][seg * 8] = *(const int4*)(g_vt_l + (size_t)(h * 32 + row) * NN + k0 + seg * 8);
        }
        __syncthreads();

        // ---- scores: 8 n-tiles of 8 keys ----
        float sc[8][4] = {};
#pragma unroll
        for (int ks = 0; ks < 2; ks++)
#pragma unroll
            for (int g = 0; g < 4; g++) {
                uint32_t bh[4], bl[4];
                LDSM4(bh, &Kh[g * 16 + b_n][ks * 16 + b_k]);
                LDSM4(bl, &Kl[g * 16 + b_n][ks * 16 + b_k]);
                MMA_F16(sc[2 * g],     qf_h[ks], bh[0], bh[1]);
                MMA_F16(sc[2 * g],     qf_l[ks], bh[0], bh[1]);
                MMA_F16(sc[2 * g],     qf_h[ks], bl[0], bl[1]);
                MMA_F16(sc[2 * g + 1], qf_h[ks], bh[2], bh[3]);
                MMA_F16(sc[2 * g + 1], qf_l[ks], bh[2], bh[3]);
                MMA_F16(sc[2 * g + 1], qf_h[ks], bl[2], bl[3]);
            }

        // ---- + mask*log2e, exp2, pack P fragments ----
        uint32_t P[4][4];
#pragma unroll
        for (int nt = 0; nt < 8; nt++) {
            const float2 mA = *(const float2*)(mask + (size_t)mrow * NN + k0 + nt * 8 + mcol);
            const float2 mB = *(const float2*)(mask + (size_t)(mrow + 8) * NN + k0 + nt * 8 + mcol);
            sc[nt][0] = fmaf(mA.x, LOG2E, sc[nt][0]);
            sc[nt][1] = fmaf(mA.y, LOG2E, sc[nt][1]);
            sc[nt][2] = fmaf(mB.x, LOG2E, sc[nt][2]);
            sc[nt][3] = fmaf(mB.y, LOG2E, sc[nt][3]);
            uint32_t e01, e23;
            CVT_F16X2(e01, sc[nt][1], sc[nt][0]);   // lo = c0
            CVT_F16X2(e23, sc[nt][3], sc[nt][2]);
            EX2_F16X2(e01);
            EX2_F16X2(e23);
            P[nt >> 1][(nt & 1) * 2]     = e01;
            P[nt >> 1][(nt & 1) * 2 + 1] = e23;
        }

        // ---- PV: 5 hi n-tiles (incl. l), 4 lo n-tiles ----
#pragma unroll
        for (int g = 0; g < 4; g++) {
            uint32_t v0h[4], v1h[4], v2h[4], v0l[4], v1l[4];
            LDSM4(v0h, &Vh[b_n][g * 16 + b_k]);
            LDSM4(v1h, &Vh[16 + b_n][g * 16 + b_k]);
            LDSM4(v2h, &Vh[32 + b_n][g * 16 + b_k]);
            LDSM4(v0l, &Vl[b_n][g * 16 + b_k]);
            LDSM4(v1l, &Vl[16 + b_n][g * 16 + b_k]);
            MMA_F16(o[0], P[g], v0h[0], v0h[1]);
            MMA_F16(o[1], P[g], v0h[2], v0h[3]);
            MMA_F16(o[2], P[g], v1h[0], v1h[1]);
            MMA_F16(o[3], P[g], v1h[2], v1h[3]);
            MMA_F16(o[4], P[g], v2h[0], v2h[1]);   // l tile (col 32 = ones)
            MMA_F16(o[0], P[g], v0l[0], v0l[1]);
            MMA_F16(o[1], P[g], v0l[2], v0l[3]);
            MMA_F16(o[2], P[g], v1l[0], v1l[1]);
            MMA_F16(o[3], P[g], v1l[2], v1l[3]);
        }
    }

    // epilogue: l lives in o[4][0]/o[4][2] of lanes with (lane&3)==0, col 32
    float lr0 = __shfl_sync(0xffffffffu, o[4][0], lane & 28);
    float lr1 = __shfl_sync(0xffffffffu, o[4][2], lane & 28);
    float s0 = 0.5f / lr0, s1 = 0.5f / lr1;
    int orow = r0 + warp * 16 + (lane >> 2);
    int ocol = h * 32 + 2 * (lane & 3);
#pragma unroll
    for (int nt = 0; nt < 4; nt++) {
        *(float2*)(g_x + (size_t)orow * DD + ocol + nt * 8) =
            make_float2(o[nt][0] * s0, o[nt][1] * s0);
        *(float2*)(g_x + (size_t)(orow + 8) * DD + ocol + nt * 8) =
            make_float2(o[nt][2] * s1, o[nt][3] * s1);
    }
}

// ================================================================
// Adjacency pass: row sums -> g_inv, fp32 -> f16 hi/lo planes
// ================================================================
__global__ __launch_bounds__(256) void rowsum_split_kernel(const float* __restrict__ adj) {
    int row = blockIdx.x;
    const float4* r4 = (const float4*)(adj + (size_t)row * NN);
    __half* hi = g_adj_h + (size_t)row * NN;
    __half* lo = g_adj_l + (size_t)row * NN;
    float s = 0.f;
    for (int i = threadIdx.x; i < NN / 4; i += 256) {
        float4 t = r4[i];
        s += t.x + t.y + t.z + t.w;
        __half hx = __float2half(t.x), hy = __float2half(t.y);
        __half hz = __float2half(t.z), hw = __float2half(t.w);
        *(uint2*)(hi + i * 4) = make_uint2(hpack(hx, hy), hpack(hz, hw));
        *(uint2*)(lo + i * 4) = make_uint2(
            hpack(__float2half(t.x - __half2float(hx)), __float2half(t.y - __half2float(hy))),
            hpack(__float2half(t.z - __half2float(hz)), __float2half(t.w - __half2float(hw))));
    }
#pragma unroll
    for (int o = 16; o > 0; o >>= 1) s += __shfl_xor_sync(0xffffffffu, s, o);
    __shared__ float red[8];
    if ((threadIdx.x & 31) == 0) red[threadIdx.x >> 5] = s;
    __syncthreads();
    if (threadIdx.x < 8) {
        float t = red[threadIdx.x];
#pragma unroll
        for (int o = 4; o > 0; o >>= 1) t += __shfl_xor_sync(0xffu, t, o);
        if (threadIdx.x == 0) g_inv[row] = 0.5f / (t + 1e-6f);
    }
}

// ================================================================
// Adjacency GEMM (mma.sync f16 hi/lo): g_x[m,n] += g_inv[m]*sum_k adj*V
// CTA 64x64, BK=32, 256 thr / 8 warps. grid (32, 4).
// ================================================================
__global__ __launch_bounds__(256) void gemm_adj_mma() {
    __shared__ __align__(16) __half Ahi[64][40], Alo[64][40];
    __shared__ __align__(16) __half Bhi[64][40], Blo[64][40];

    int tid = threadIdx.x;
    int wid = tid >> 5, lane = tid & 31;
    int m0 = blockIdx.x * 64, n0 = blockIdx.y * 64;
    int wm = (wid >> 2) * 32;
    int wn = (wid & 3) * 16;

    int a_m = lane & 15, a_k = (lane >> 4) << 3;
    int b_n = (lane & 7) + ((lane >> 4) << 3);
    int b_k = ((lane >> 3) & 1) << 3;
    int lr = tid >> 2, lc = (tid & 3) * 8;

    float acc[2][2][4] = {};

    for (int kb = 0; kb < NN / 32; kb++) {
        int k0 = kb * 32;
        *(int4*)&Ahi[lr][lc] = *(const int4*)(g_adj_h + (size_t)(m0 + lr) * NN + k0 + lc);
        *(int4*)&Alo[lr][lc] = *(const int4*)(g_adj_l + (size_t)(m0 + lr) * NN + k0 + lc);
        *(int4*)&Bhi[lr][lc] = *(const int4*)(g_vt_h + (size_t)(n0 + lr) * NN + k0 + lc);
        *(int4*)&Blo[lr][lc] = *(const int4*)(g_vt_l + (size_t)(n0 + lr) * NN + k0 + lc);
        __syncthreads();

#pragma unroll
        for (int ks = 0; ks < 2; ks++) {
            int kk = ks * 16;
            uint32_t ahi[2][4], alo[2][4], bhi[4], blo[4];
#pragma unroll
            for (int mt = 0; mt < 2; mt++) {
                LDSM4(ahi[mt], &Ahi[wm + mt * 16 + a_m][kk + a_k]);
                LDSM4(alo[mt], &Alo[wm + mt * 16 + a_m][kk + a_k]);
            }
            LDSM4(bhi, &Bhi[wn + b_n][kk + b_k]);
            LDSM4(blo, &Blo[wn + b_n][kk + b_k]);

#pragma unroll
            for (int mt = 0; mt < 2; mt++)
#pragma unroll
                for (int nt = 0; nt < 2; nt++) {
                    MMA_F16(acc[mt][nt], ahi[mt], bhi[nt * 2], bhi[nt * 2 + 1]);
                    MMA_F16(acc[mt][nt], alo[mt], bhi[nt * 2], bhi[nt * 2 + 1]);
                    MMA_F16(acc[mt][nt], ahi[mt], blo[nt * 2], blo[nt * 2 + 1]);
                }
        }
        __syncthreads();
    }

    int rbase = wm + (lane >> 2);
    int cbase = wn + 2 * (lane & 3);
#pragma unroll
    for (int mt = 0; mt < 2; mt++) {
        int r = m0 + rbase + mt * 16;
        float rs0 = g_inv[r], rs1 = g_inv[r + 8];
#pragma unroll
        for (int nt = 0; nt < 2; nt++) {
            int c = n0 + cbase + nt * 8;
            float2 p0 = *(float2*)(g_x + (size_t)r * DD + c);
            float2 p1 = *(float2*)(g_x + (size_t)(r + 8) * DD + c);
            p0.x += acc[mt][nt][0] * rs0; p0.y += acc[mt][nt][1] * rs0;
            p1.x += acc[mt][nt][2] * rs1; p1.y += acc[mt][nt][3] * rs1;
            *(float2*)(g_x + (size_t)r * DD + c) = p0;
            *(float2*)(g_x + (size_t)(r + 8) * DD + c) = p1;
        }
    }
}

// ================================================================
extern "C" void kernel_launch(void* const* d_in, const int* in_sizes, int n_in,
                              void* d_out, int out_size) {
    const float* query = (const float*)d_in[0];
    const float* key   = (const float*)d_in[1];
    const float* value = (const float*)d_in[2];
    const float* mask  = (const float*)d_in[3];
    const float* adj   = (const float*)d_in[4];
    const float* Wq = (const float*)d_in[5];  const float* bq = (const float*)d_in[6];
    const float* Wk = (const float*)d_in[7];  const float* bk = (const float*)d_in[8];
    const float* Wv = (const float*)d_in[9];  const float* bv = (const float*)d_in[10];
    const float* Wo = (const float*)d_in[11]; const float* bo = (const float*)d_in[12];
    float* out = (float*)d_out;

    float* px;
    cudaGetSymbolAddress((void**)&px, g_x);

    dim3 pgrid(NN / 32, DD / 64);

    // 1-3: projections with fused f16 hi/lo conversion
    gemm_proj<<<pgrid, 128>>>(query, Wq, bq, nullptr, 0);
    gemm_proj<<<pgrid, 128>>>(key,   Wk, bk, nullptr, 1);
    gemm_proj<<<pgrid, 128>>>(value, Wv, bv, nullptr, 2);

    // 4: tensor-core flash attention -> g_x = 0.5*attn
    attn_mma<<<dim3(NN / 128, HH), 256>>>(mask);

    // 5: adjacency row sums + f16 planes
    rowsum_split_kernel<<<NN, 256>>>(adj);

    // 6: g_x += 0.5 * p_adj @ V (tensor cores)
    gemm_adj_mma<<<dim3(NN / 64, DD / 64), 256>>>();

    // 7: output projection
    gemm_proj<<<pgrid, 128>>>(px, Wo, bo, out, 3);
}

// round 15
// speedup vs baseline: 3.2202x; 1.0681x over previous
#include <cuda_runtime.h>
#include <cuda_fp16.h>
#include <math.h>
#include <stdint.h>

#define NN 2048
#define DD 256
#define HH 8

// ---------------- scratch (static device globals; no allocation) ----------------
__device__ float g_inv[NN];                 // 0.5 / (rowsum + eps)
__device__ float g_x[NN * DD];              // 0.5*attn (+ 0.5*p_adj@V accumulated)
__device__ __half g_qh_h[NN * DD];          // Q * (log2e/sqrt(32)), f16 hi
__device__ __half g_qh_l[NN * DD];          //   f16 lo
__device__ __half g_kh_h[NN * DD];          // K f16 hi/lo
__device__ __half g_kh_l[NN * DD];
__device__ __half g_vt_h[DD * NN];          // V^T [d][n] f16 hi/lo
__device__ __half g_vt_l[DD * NN];
__device__ __half g_adj_h[NN * NN];         // adj f16 hi/lo [m][k]
__device__ __half g_adj_l[NN * NN];
__device__ __half g_w_h[4 * DD * DD];       // Wq,Wk,Wv,Wo f16 hi ([n][k])
__device__ __half g_w_l[4 * DD * DD];       //   f16 lo

#define LOG2E 1.4426950408889634f
#define QSCALE 0.25508218912f   /* log2e / sqrt(32) */

// ---------------- helpers ----------------
__device__ __forceinline__ uint32_t smem_u32(const void* p) {
    uint32_t a;
    asm("{ .reg .u64 t; cvta.to.shared.u64 t, %1; cvt.u32.u64 %0, t; }" : "=r"(a) : "l"(p));
    return a;
}
__device__ __forceinline__ uint32_t hpack(__half a, __half b) {
    return (uint32_t)__half_as_ushort(a) | ((uint32_t)__half_as_ushort(b) << 16);
}

#define MMA_F16(d, a, b0, b1)                                                   \
    asm volatile("mma.sync.aligned.m16n8k16.row.col.f32.f16.f16.f32 "          \
        "{%0,%1,%2,%3}, {%4,%5,%6,%7}, {%8,%9}, {%0,%1,%2,%3};"                \
        : "+f"((d)[0]), "+f"((d)[1]), "+f"((d)[2]), "+f"((d)[3])               \
        : "r"((a)[0]), "r"((a)[1]), "r"((a)[2]), "r"((a)[3]), "r"(b0), "r"(b1))

#define LDSM4(r, ptr)                                                           \
    asm volatile("ldmatrix.sync.aligned.m8n8.x4.shared.b16 {%0,%1,%2,%3}, [%4];" \
        : "=r"((r)[0]), "=r"((r)[1]), "=r"((r)[2]), "=r"((r)[3]) : "r"(smem_u32(ptr)))

#define CVT_F16X2(d, a, b) \
    asm("cvt.rn.f16x2.f32 %0, %1, %2;" : "=r"(d) : "f"(a), "f"(b))
#define EX2_F16X2(d) \
    asm("ex2.approx.f16x2 %0, %0;" : "+r"(d))

// ================================================================
// Weight split-convert: W fp32 [n][k] -> Wh/Wl f16. grid 64, 256 thr.
// ================================================================
__global__ __launch_bounds__(256) void wconvert(const float* __restrict__ W,
                                                __half* __restrict__ Wh,
                                                __half* __restrict__ Wl) {
    int i = blockIdx.x * 256 + threadIdx.x;
    float4 f = ((const float4*)W)[i];
    __half hx = __float2half(f.x), hy = __float2half(f.y);
    __half hz = __float2half(f.z), hw = __float2half(f.w);
    *(uint2*)(Wh + (size_t)i * 4) = make_uint2(hpack(hx, hy), hpack(hz, hw));
    *(uint2*)(Wl + (size_t)i * 4) = make_uint2(
        hpack(__float2half(f.x - __half2float(hx)), __float2half(f.y - __half2float(hy))),
        hpack(__float2half(f.z - __half2float(hz)), __float2half(f.w - __half2float(hw))));
}

// ================================================================
// Tensorized projection: C[2048,256] = A @ W^T + b.
// CTA 64x64, BK=32, 8 warps, f16 hi/lo 3-term. Epilogue mode:
//   0: q -> g_qh hi/lo scaled by QSCALE   1: k -> g_kh hi/lo
//   2: v -> transposed into g_vt hi/lo    3: fp32 -> Cout
// stage stride = 68 floats (272 B, 16B-multiple -> float4-safe)
// ================================================================
__global__ __launch_bounds__(256) void gemm_proj_mma(const float* __restrict__ A,
                                                     const __half* __restrict__ Wh,
                                                     const __half* __restrict__ Wl,
                                                     const float* __restrict__ bias,
                                                     float* __restrict__ Cout,
                                                     int mode) {
    __shared__ __align__(16) char sm[20480];
    __half* Ahi = (__half*)sm;              // [64][40]
    __half* Alo = (__half*)(sm + 5120);
    __half* Bhi = (__half*)(sm + 10240);
    __half* Blo = (__half*)(sm + 15360);
    float* stage = (float*)sm;              // overlay [64][68] = 17408 B

    int tid = threadIdx.x, wid = tid >> 5, lane = tid & 31;
    int m0 = blockIdx.x * 64, n0 = blockIdx.y * 64;
    int wm = (wid >> 2) * 32, wn = (wid & 3) * 16;
    int a_m = lane & 15, a_k = (lane >> 4) << 3;
    int b_n = (lane & 7) + ((lane >> 4) << 3);
    int b_k = ((lane >> 3) & 1) << 3;
    int lr = tid >> 2, lc8 = (tid & 3) * 8;

    float acc[2][2][4] = {};

    for (int kb = 0; kb < 8; kb++) {
        int k0 = kb * 32;
        {   // A tile 64x32 fp32 -> hi/lo
            const float4* pa = (const float4*)(A + (size_t)(m0 + lr) * DD + k0 + lc8);
            float4 f0 = pa[0], f1 = pa[1];
            float v[8] = {f0.x, f0.y, f0.z, f0.w, f1.x, f1.y, f1.z, f1.w};
            __half hb[8], lb[8];
#pragma unroll
            for (int e = 0; e < 8; e++) {
                hb[e] = __float2half(v[e]);
                lb[e] = __float2half(v[e] - __half2float(hb[e]));
            }
            int4 ph, pl;
            ph.x = hpack(hb[0], hb[1]); ph.y = hpack(hb[2], hb[3]);
            ph.z = hpack(hb[4], hb[5]); ph.w = hpack(hb[6], hb[7]);
            pl.x = hpack(lb[0], lb[1]); pl.y = hpack(lb[2], lb[3]);
            pl.z = hpack(lb[4], lb[5]); pl.w = hpack(lb[6], lb[7]);
            *(int4*)&Ahi[lr * 40 + lc8] = ph;
            *(int4*)&Alo[lr * 40 + lc8] = pl;
        }
        {   // W tile (pre-split)
            *(int4*)&Bhi[lr * 40 + lc8] = *(const int4*)(Wh + (size_t)(n0 + lr) * DD + k0 + lc8);
            *(int4*)&Blo[lr * 40 + lc8] = *(const int4*)(Wl + (size_t)(n0 + lr) * DD + k0 + lc8);
        }
        __syncthreads();
#pragma unroll
        for (int ks = 0; ks < 2; ks++) {
            int kk = ks * 16;
            uint32_t ahi[2][4], alo[2][4], bhi[4], blo[4];
#pragma unroll
            for (int mt = 0; mt < 2; mt++) {
                LDSM4(ahi[mt], &Ahi[(wm + mt * 16 + a_m) * 40 + kk + a_k]);
                LDSM4(alo[mt], &Alo[(wm + mt * 16 + a_m) * 40 + kk + a_k]);
            }
            LDSM4(bhi, &Bhi[(wn + b_n) * 40 + kk + b_k]);
            LDSM4(blo, &Blo[(wn + b_n) * 40 + kk + b_k]);
#pragma unroll
            for (int mt = 0; mt < 2; mt++)
#pragma unroll
                for (int nt = 0; nt < 2; nt++) {
                    MMA_F16(acc[mt][nt], ahi[mt], bhi[nt * 2], bhi[nt * 2 + 1]);
                    MMA_F16(acc[mt][nt], alo[mt], bhi[nt * 2], bhi[nt * 2 + 1]);
                    MMA_F16(acc[mt][nt], ahi[mt], blo[nt * 2], blo[nt * 2 + 1]);
                }
        }
        __syncthreads();
    }

    // bias + scale, stage to smem
    int rbase = wm + (lane >> 2), cbase = wn + 2 * (lane & 3);
    float scl = (mode == 0) ? QSCALE : 1.0f;
#pragma unroll
    for (int nt = 0; nt < 2; nt++) {
        int c = cbase + nt * 8;
        float b0 = bias[n0 + c], b1 = bias[n0 + c + 1];
#pragma unroll
        for (int mt = 0; mt < 2; mt++) {
            int r = rbase + mt * 16;
            stage[r * 68 + c]           = (acc[mt][nt][0] + b0) * scl;
            stage[r * 68 + c + 1]       = (acc[mt][nt][1] + b1) * scl;
            stage[(r + 8) * 68 + c]     = (acc[mt][nt][2] + b0) * scl;
            stage[(r + 8) * 68 + c + 1] = (acc[mt][nt][3] + b1) * scl;
        }
    }
    __syncthreads();

    if (mode == 3) {
        int row = tid >> 2, c0 = (tid & 3) * 16;
#pragma unroll
        for (int e = 0; e < 4; e++) {
            float4 o = *(float4*)&stage[row * 68 + c0 + e * 4];
            *(float4*)(Cout + (size_t)(m0 + row) * DD + n0 + c0 + e * 4) = o;
        }
        return;
    }

    if (mode == 2) {
        int dl = tid >> 2, ml0 = (tid & 3) * 16;
        __half hb[16], lb[16];
#pragma unroll
        for (int e = 0; e < 16; e++) {
            float v = stage[(ml0 + e) * 68 + dl];
            hb[e] = __float2half(v);
            lb[e] = __float2half(v - __half2float(hb[e]));
        }
        size_t off = (size_t)(n0 + dl) * NN + m0 + ml0;
#pragma unroll
        for (int c = 0; c < 2; c++) {
            int4 ph, pl;
            ph.x = hpack(hb[c*8+0], hb[c*8+1]); ph.y = hpack(hb[c*8+2], hb[c*8+3]);
            ph.z = hpack(hb[c*8+4], hb[c*8+5]); ph.w = hpack(hb[c*8+6], hb[c*8+7]);
            pl.x = hpack(lb[c*8+0], lb[c*8+1]); pl.y = hpack(lb[c*8+2], lb[c*8+3]);
            pl.z = hpack(lb[c*8+4], lb[c*8+5]); pl.w = hpack(lb[c*8+6], lb[c*8+7]);
            *(int4*)(g_vt_h + off + c * 8) = ph;
            *(int4*)(g_vt_l + off + c * 8) = pl;
        }
        return;
    }

    // mode 0/1
    __half* Hh = (mode == 0) ? g_qh_h : g_kh_h;
    __half* Hl = (mode == 0) ? g_qh_l : g_kh_l;
    int row = tid >> 2, c0 = (tid & 3) * 16;
    __half hb[16], lb[16];
#pragma unroll
    for (int e = 0; e < 16; e++) {
        float v = stage[row * 68 + c0 + e];
        hb[e] = __float2half(v);
        lb[e] = __float2half(v - __half2float(hb[e]));
    }
    size_t off = (size_t)(m0 + row) * DD + n0 + c0;
#pragma unroll
    for (int c = 0; c < 2; c++) {
        int4 ph, pl;
        ph.x = hpack(hb[c*8+0], hb[c*8+1]); ph.y = hpack(hb[c*8+2], hb[c*8+3]);
        ph.z = hpack(hb[c*8+4], hb[c*8+5]); ph.w = hpack(hb[c*8+6], hb[c*8+7]);
        pl.x = hpack(lb[c*8+0], lb[c*8+1]); pl.y = hpack(lb[c*8+2], lb[c*8+3]);
        pl.z = hpack(lb[c*8+4], lb[c*8+5]); pl.w = hpack(lb[c*8+6], lb[c*8+7]);
        *(int4*)(Hh + off + c * 8) = ph;
        *(int4*)(Hl + off + c * 8) = pl;
    }
}

// ================================================================
// Flash attention via mma.sync. CTA = (128 rows, 1 head), 512 thr / 16 warps.
// Warp-group wg (0/1) handles key n-tiles 4wg..4wg+3; warp wr owns rows
// 16wr..16wr+15. Partial (o,l) are additive (no-max softmax) -> smem merge.
// ================================================================
__global__ __launch_bounds__(512) void attn_mma(const float* __restrict__ mask) {
    __shared__ __align__(16) char sm[44544];
    __half* Qh = (__half*)sm;               // [128][40]
    __half* Ql = (__half*)(sm + 10240);
    __half* Kh = (__half*)(sm + 20480);     // [64][40]
    __half* Kl = (__half*)(sm + 25600);
    __half* Vh = (__half*)(sm + 30720);     // [48][72]
    __half* Vl = (__half*)(sm + 37632);
    float* stage = (float*)(sm + 20480);    // overlay: [8*32][21] floats

    int tid = threadIdx.x, warp = tid >> 5, lane = tid & 31;
    int wg = warp >> 3, wr = warp & 7;
    int h = blockIdx.y, r0 = blockIdx.x * 128;

    {   // Q tile (128x32) hi/lo: one int4 pair per thread
        int row = tid >> 2, seg = tid & 3;
        *(int4*)&Qh[row * 40 + seg * 8] = *(const int4*)(g_qh_h + (size_t)(r0 + row) * DD + h * 32 + seg * 8);
        *(int4*)&Ql[row * 40 + seg * 8] = *(const int4*)(g_qh_l + (size_t)(r0 + row) * DD + h * 32 + seg * 8);
    }
    // V static rows 32..47: row 32 = ones (l accumulator), rest zero
    for (int i = tid; i < 16 * 72; i += 512) {
        int r = 32 + i / 72, c = i % 72;
        Vh[r * 72 + c] = (r == 32) ? __float2half(1.0f) : __ushort_as_half(0);
        Vl[r * 72 + c] = __ushort_as_half(0);
    }
    __syncthreads();

    uint32_t qf_h[2][4], qf_l[2][4];
    int a_m = lane & 15, a_k = (lane >> 4) << 3;
#pragma unroll
    for (int ks = 0; ks < 2; ks++) {
        LDSM4(qf_h[ks], &Qh[(wr * 16 + a_m) * 40 + ks * 16 + a_k]);
        LDSM4(qf_l[ks], &Ql[(wr * 16 + a_m) * 40 + ks * 16 + a_k]);
    }

    int b_n = (lane & 7) + ((lane >> 4) << 3);
    int b_k = ((lane >> 3) & 1) << 3;
    int mrow = r0 + wr * 16 + (lane >> 2);
    int mcol = 2 * (lane & 3);

    float o[5][4] = {};

    for (int kt = 0; kt < 32; kt++) {
        int k0 = kt * 64;
        __syncthreads();
        if (tid < 256) {   // K tile: 64x32 hi/lo
            int row = tid >> 2, seg = tid & 3;
            *(int4*)&Kh[row * 40 + seg * 8] = *(const int4*)(g_kh_h + (size_t)(k0 + row) * DD + h * 32 + seg * 8);
            *(int4*)&Kl[row * 40 + seg * 8] = *(const int4*)(g_kh_l + (size_t)(k0 + row) * DD + h * 32 + seg * 8);
        } else {           // V^T tile: 32x64 hi/lo
            int t = tid - 256, row = t >> 3, seg = t & 7;
            *(int4*)&Vh[row * 72 + seg * 8] = *(const int4*)(g_vt_h + (size_t)(h * 32 + row) * NN + k0 + seg * 8);
            *(int4*)&Vl[row * 72 + seg * 8] = *(const int4*)(g_vt_l + (size_t)(h * 32 + row) * NN + k0 + seg * 8);
        }
        __syncthreads();

        // ---- scores: this wg's 4 n-tiles (2 key-groups of 16) ----
        float sc[4][4] = {};
#pragma unroll
        for (int ks = 0; ks < 2; ks++)
#pragma unroll
            for (int gl = 0; gl < 2; gl++) {
                int g = 2 * wg + gl;
                uint32_t bh[4], bl[4];
                LDSM4(bh, &Kh[(g * 16 + b_n) * 40 + ks * 16 + b_k]);
                LDSM4(bl, &Kl[(g * 16 + b_n) * 40 + ks * 16 + b_k]);
                MMA_F16(sc[2 * gl],     qf_h[ks], bh[0], bh[1]);
                MMA_F16(sc[2 * gl],     qf_l[ks], bh[0], bh[1]);
                MMA_F16(sc[2 * gl],     qf_h[ks], bl[0], bl[1]);
                MMA_F16(sc[2 * gl + 1], qf_h[ks], bh[2], bh[3]);
                MMA_F16(sc[2 * gl + 1], qf_l[ks], bh[2], bh[3]);
                MMA_F16(sc[2 * gl + 1], qf_h[ks], bl[2], bl[3]);
            }

        // ---- + mask*log2e, exp2, pack P ----
        uint32_t P[2][4];
#pragma unroll
        for (int ntl = 0; ntl < 4; ntl++) {
            int nt = 4 * wg + ntl;
            const float2 mA = *(const float2*)(mask + (size_t)mrow * NN + k0 + nt * 8 + mcol);
            const float2 mB = *(const float2*)(mask + (size_t)(mrow + 8) * NN + k0 + nt * 8 + mcol);
            sc[ntl][0] = fmaf(mA.x, LOG2E, sc[ntl][0]);
            sc[ntl][1] = fmaf(mA.y, LOG2E, sc[ntl][1]);
            sc[ntl][2] = fmaf(mB.x, LOG2E, sc[ntl][2]);
            sc[ntl][3] = fmaf(mB.y, LOG2E, sc[ntl][3]);
            uint32_t e01, e23;
            CVT_F16X2(e01, sc[ntl][1], sc[ntl][0]);
            CVT_F16X2(e23, sc[ntl][3], sc[ntl][2]);
            EX2_F16X2(e01);
            EX2_F16X2(e23);
            P[ntl >> 1][(ntl & 1) * 2]     = e01;
            P[ntl >> 1][(ntl & 1) * 2 + 1] = e23;
        }

        // ---- PV over this wg's 2 key-groups ----
#pragma unroll
        for (int gl = 0; gl < 2; gl++) {
            int g = 2 * wg + gl;
            uint32_t v0h[4], v1h[4], v2h[4], v0l[4], v1l[4];
            LDSM4(v0h, &Vh[b_n * 72 + g * 16 + b_k]);
            LDSM4(v1h, &Vh[(16 + b_n) * 72 + g * 16 + b_k]);
            LDSM4(v2h, &Vh[(32 + b_n) * 72 + g * 16 + b_k]);
            LDSM4(v0l, &Vl[b_n * 72 + g * 16 + b_k]);
            LDSM4(v1l, &Vl[(16 + b_n) * 72 + g * 16 + b_k]);
            MMA_F16(o[0], P[gl], v0h[0], v0h[1]);
            MMA_F16(o[1], P[gl], v0h[2], v0h[3]);
            MMA_F16(o[2], P[gl], v1h[0], v1h[1]);
            MMA_F16(o[3], P[gl], v1h[2], v1h[3]);
            MMA_F16(o[4], P[gl], v2h[0], v2h[1]);   // l tile (col 32 = ones)
            MMA_F16(o[0], P[gl], v0l[0], v0l[1]);
            MMA_F16(o[1], P[gl], v0l[2], v0l[3]);
            MMA_F16(o[2], P[gl], v1l[0], v1l[1]);
            MMA_F16(o[3], P[gl], v1l[2], v1l[3]);
        }
    }

    // ---- merge wg1 partials into wg0, then write ----
    __syncthreads();
    if (wg == 1) {
        float* s = stage + (wr * 32 + lane) * 21;
#pragma unroll
        for (int i = 0; i < 5; i++)
#pragma unroll
            for (int j = 0; j < 4; j++) s[i * 4 + j] = o[i][j];
    }
    __syncthreads();
    if (wg == 0) {
        float* s = stage + (wr * 32 + lane) * 21;
#pragma unroll
        for (int i = 0; i < 5; i++)
#pragma unroll
            for (int j = 0; j < 4; j++) o[i][j] += s[i * 4 + j];

        float lr0 = __shfl_sync(0xffffffffu, o[4][0], lane & 28);
        float lr1 = __shfl_sync(0xffffffffu, o[4][2], lane & 28);
        float s0 = 0.5f / lr0, s1 = 0.5f / lr1;
        int orow = r0 + wr * 16 + (lane >> 2);
        int ocol = h * 32 + 2 * (lane & 3);
#pragma unroll
        for (int nt = 0; nt < 4; nt++) {
            *(float2*)(g_x + (size_t)orow * DD + ocol + nt * 8) =
                make_float2(o[nt][0] * s0, o[nt][1] * s0);
            *(float2*)(g_x + (size_t)(orow + 8) * DD + ocol + nt * 8) =
                make_float2(o[nt][2] * s1, o[nt][3] * s1);
        }
    }
}

// ================================================================
// Adjacency pass: row sums -> g_inv, fp32 -> f16 hi/lo planes
// ================================================================
__global__ __launch_bounds__(256) void rowsum_split_kernel(const float* __restrict__ adj) {
    int row = blockIdx.x;
    const float4* r4 = (const float4*)(adj + (size_t)row * NN);
    __half* hi = g_adj_h + (size_t)row * NN;
    __half* lo = g_adj_l + (size_t)row * NN;
    float s = 0.f;
    for (int i = threadIdx.x; i < NN / 4; i += 256) {
        float4 t = r4[i];
        s += t.x + t.y + t.z + t.w;
        __half hx = __float2half(t.x), hy = __float2half(t.y);
        __half hz = __float2half(t.z), hw = __float2half(t.w);
        *(uint2*)(hi + i * 4) = make_uint2(hpack(hx, hy), hpack(hz, hw));
        *(uint2*)(lo + i * 4) = make_uint2(
            hpack(__float2half(t.x - __half2float(hx)), __float2half(t.y - __half2float(hy))),
            hpack(__float2half(t.z - __half2float(hz)), __float2half(t.w - __half2float(hw))));
    }
#pragma unroll
    for (int o = 16; o > 0; o >>= 1) s += __shfl_xor_sync(0xffffffffu, s, o);
    __shared__ float red[8];
    if ((threadIdx.x & 31) == 0) red[threadIdx.x >> 5] = s;
    __syncthreads();
    if (threadIdx.x < 8) {
        float t = red[threadIdx.x];
#pragma unroll
        for (int o = 4; o > 0; o >>= 1) t += __shfl_xor_sync(0xffu, t, o);
        if (threadIdx.x == 0) g_inv[row] = 0.5f / (t + 1e-6f);
    }
}

// ================================================================
// Adjacency GEMM (mma.sync f16 hi/lo): g_x[m,n] += g_inv[m]*sum_k adj*V
// CTA 64x64, BK=32, 256 thr / 8 warps. grid (32, 4).
// ================================================================
__global__ __launch_bounds__(256) void gemm_adj_mma() {
    __shared__ __align__(16) __half Ahi[64][40], Alo[64][40];
    __shared__ __align__(16) __half Bhi[64][40], Blo[64][40];

    int tid = threadIdx.x;
    int wid = tid >> 5, lane = tid & 31;
    int m0 = blockIdx.x * 64, n0 = blockIdx.y * 64;
    int wm = (wid >> 2) * 32;
    int wn = (wid & 3) * 16;

    int a_m = lane & 15, a_k = (lane >> 4) << 3;
    int b_n = (lane & 7) + ((lane >> 4) << 3);
    int b_k = ((lane >> 3) & 1) << 3;
    int lr = tid >> 2, lc = (tid & 3) * 8;

    float acc[2][2][4] = {};

    for (int kb = 0; kb < NN / 32; kb++) {
        int k0 = kb * 32;
        *(int4*)&Ahi[lr][lc] = *(const int4*)(g_adj_h + (size_t)(m0 + lr) * NN + k0 + lc);
        *(int4*)&Alo[lr][lc] = *(const int4*)(g_adj_l + (size_t)(m0 + lr) * NN + k0 + lc);
        *(int4*)&Bhi[lr][lc] = *(const int4*)(g_vt_h + (size_t)(n0 + lr) * NN + k0 + lc);
        *(int4*)&Blo[lr][lc] = *(const int4*)(g_vt_l + (size_t)(n0 + lr) * NN + k0 + lc);
        __syncthreads();

#pragma unroll
        for (int ks = 0; ks < 2; ks++) {
            int kk = ks * 16;
            uint32_t ahi[2][4], alo[2][4], bhi[4], blo[4];
#pragma unroll
            for (int mt = 0; mt < 2; mt++) {
                LDSM4(ahi[mt], &Ahi[wm + mt * 16 + a_m][kk + a_k]);
                LDSM4(alo[mt], &Alo[wm + mt * 16 + a_m][kk + a_k]);
            }
            LDSM4(bhi, &Bhi[wn + b_n][kk + b_k]);
            LDSM4(blo, &Blo[wn + b_n][kk + b_k]);

#pragma unroll
            for (int mt = 0; mt < 2; mt++)
#pragma unroll
                for (int nt = 0; nt < 2; nt++) {
                    MMA_F16(acc[mt][nt], ahi[mt], bhi[nt * 2], bhi[nt * 2 + 1]);
                    MMA_F16(acc[mt][nt], alo[mt], bhi[nt * 2], bhi[nt * 2 + 1]);
                    MMA_F16(acc[mt][nt], ahi[mt], blo[nt * 2], blo[nt * 2 + 1]);
                }
        }
        __syncthreads();
    }

    int rbase = wm + (lane >> 2);
    int cbase = wn + 2 * (lane & 3);
#pragma unroll
    for (int mt = 0; mt < 2; mt++) {
        int r = m0 + rbase + mt * 16;
        float rs0 = g_inv[r], rs1 = g_inv[r + 8];
#pragma unroll
        for (int nt = 0; nt < 2; nt++) {
            int c = n0 + cbase + nt * 8;
            float2 p0 = *(float2*)(g_x + (size_t)r * DD + c);
            float2 p1 = *(float2*)(g_x + (size_t)(r + 8) * DD + c);
            p0.x += acc[mt][nt][0] * rs0; p0.y += acc[mt][nt][1] * rs0;
            p1.x += acc[mt][nt][2] * rs1; p1.y += acc[mt][nt][3] * rs1;
            *(float2*)(g_x + (size_t)r * DD + c) = p0;
            *(float2*)(g_x + (size_t)(r + 8) * DD + c) = p1;
        }
    }
}

// ================================================================
extern "C" void kernel_launch(void* const* d_in, const int* in_sizes, int n_in,
                              void* d_out, int out_size) {
    const float* query = (const float*)d_in[0];
    const float* key   = (const float*)d_in[1];
    const float* value = (const float*)d_in[2];
    const float* mask  = (const float*)d_in[3];
    const float* adj   = (const float*)d_in[4];
    const float* Wq = (const float*)d_in[5];  const float* bq = (const float*)d_in[6];
    const float* Wk = (const float*)d_in[7];  const float* bk = (const float*)d_in[8];
    const float* Wv = (const float*)d_in[9];  const float* bv = (const float*)d_in[10];
    const float* Wo = (const float*)d_in[11]; const float* bo = (const float*)d_in[12];
    float* out = (float*)d_out;

    float* px;
    __half *pwh, *pwl;
    cudaGetSymbolAddress((void**)&px, g_x);
    cudaGetSymbolAddress((void**)&pwh, g_w_h);
    cudaGetSymbolAddress((void**)&pwl, g_w_l);

    const int WSZ = DD * DD;

    // 0: weight splits (4 x tiny)
    wconvert<<<64, 256>>>(Wq, pwh + 0 * WSZ, pwl + 0 * WSZ);
    wconvert<<<64, 256>>>(Wk, pwh + 1 * WSZ, pwl + 1 * WSZ);
    wconvert<<<64, 256>>>(Wv, pwh + 2 * WSZ, pwl + 2 * WSZ);
    wconvert<<<64, 256>>>(Wo, pwh + 3 * WSZ, pwl + 3 * WSZ);

    dim3 pgrid(NN / 64, DD / 64);

    // 1-3: tensorized projections with fused f16 hi/lo epilogues
    gemm_proj_mma<<<pgrid, 256>>>(query, pwh + 0 * WSZ, pwl + 0 * WSZ, bq, nullptr, 0);
    gemm_proj_mma<<<pgrid, 256>>>(key,   pwh + 1 * WSZ, pwl + 1 * WSZ, bk, nullptr, 1);
    gemm_proj_mma<<<pgrid, 256>>>(value, pwh + 2 * WSZ, pwl + 2 * WSZ, bv, nullptr, 2);

    // 4: tensor-core flash attention -> g_x = 0.5*attn
    attn_mma<<<dim3(NN / 128, HH), 512>>>(mask);

    // 5: adjacency row sums + f16 planes
    rowsum_split_kernel<<<NN, 256>>>(adj);

    // 6: g_x += 0.5 * p_adj @ V (tensor cores)
    gemm_adj_mma<<<dim3(NN / 64, DD / 64), 256>>>();

    // 7: output projection (fp32 out)
    gemm_proj_mma<<<pgrid, 256>>>(px, pwh + 3 * WSZ, pwl + 3 * WSZ, bo, out, 3);
}

// round 16
// speedup vs baseline: 4.3274x; 1.3438x over previous
#include <cuda_runtime.h>
#include <cuda_fp16.h>
#include <math.h>
#include <stdint.h>

#define NN 2048
#define DD 256
#define HH 8

// ---------------- scratch (static device globals; no allocation) ----------------
__device__ float g_inv[NN];                 // 0.5 / (rowsum + eps)
__device__ float g_x[NN * DD];              // 0.5*attn (+ 0.5*p_adj@V accumulated)
__device__ __half g_qh_h[NN * DD];          // Q * (log2e/sqrt(32)), f16 hi
__device__ __half g_qh_l[NN * DD];          //   f16 lo
__device__ __half g_kh_h[NN * DD];          // K f16 hi/lo
__device__ __half g_kh_l[NN * DD];
__device__ __half g_vt_h[DD * NN];          // V^T [d][n] f16 hi/lo
__device__ __half g_vt_l[DD * NN];
__device__ __half g_w_h[4 * DD * DD];       // Wq,Wk,Wv,Wo f16 hi ([n][k])
__device__ __half g_w_l[4 * DD * DD];       //   f16 lo

#define LOG2E 1.4426950408889634f
#define QSCALE 0.25508218912f   /* log2e / sqrt(32) */

// ---------------- helpers ----------------
__device__ __forceinline__ uint32_t smem_u32(const void* p) {
    uint32_t a;
    asm("{ .reg .u64 t; cvta.to.shared.u64 t, %1; cvt.u32.u64 %0, t; }" : "=r"(a) : "l"(p));
    return a;
}
__device__ __forceinline__ uint32_t hpack(__half a, __half b) {
    return (uint32_t)__half_as_ushort(a) | ((uint32_t)__half_as_ushort(b) << 16);
}

#define MMA_F16(d, a, b0, b1)                                                   \
    asm volatile("mma.sync.aligned.m16n8k16.row.col.f32.f16.f16.f32 "          \
        "{%0,%1,%2,%3}, {%4,%5,%6,%7}, {%8,%9}, {%0,%1,%2,%3};"                \
        : "+f"((d)[0]), "+f"((d)[1]), "+f"((d)[2]), "+f"((d)[3])               \
        : "r"((a)[0]), "r"((a)[1]), "r"((a)[2]), "r"((a)[3]), "r"(b0), "r"(b1))

#define LDSM4(r, ptr)                                                           \
    asm volatile("ldmatrix.sync.aligned.m8n8.x4.shared.b16 {%0,%1,%2,%3}, [%4];" \
        : "=r"((r)[0]), "=r"((r)[1]), "=r"((r)[2]), "=r"((r)[3]) : "r"(smem_u32(ptr)))

#define CVT_F16X2(d, a, b) \
    asm("cvt.rn.f16x2.f32 %0, %1, %2;" : "=r"(d) : "f"(a), "f"(b))
#define EX2_F16X2(d) \
    asm("ex2.approx.f16x2 %0, %0;" : "+r"(d))

// split 8 fp32 -> packed hi/lo int4
__device__ __forceinline__ void split8(const float* v, int4& ph, int4& pl) {
    __half hb[8], lb[8];
#pragma unroll
    for (int e = 0; e < 8; e++) {
        hb[e] = __float2half(v[e]);
        lb[e] = __float2half(v[e] - __half2float(hb[e]));
    }
    ph.x = hpack(hb[0], hb[1]); ph.y = hpack(hb[2], hb[3]);
    ph.z = hpack(hb[4], hb[5]); ph.w = hpack(hb[6], hb[7]);
    pl.x = hpack(lb[0], lb[1]); pl.y = hpack(lb[2], lb[3]);
    pl.z = hpack(lb[4], lb[5]); pl.w = hpack(lb[6], lb[7]);
}

// ================================================================
// Fused weight split-convert: 4 weights fp32 [n][k] -> g_w hi/lo.
// grid 256 (64 blocks per weight), 256 thr.
// ================================================================
__global__ __launch_bounds__(256) void wconvert4(const float* __restrict__ W0,
                                                 const float* __restrict__ W1,
                                                 const float* __restrict__ W2,
                                                 const float* __restrict__ W3) {
    int w = blockIdx.x >> 6;
    const float* W = (w == 0) ? W0 : (w == 1) ? W1 : (w == 2) ? W2 : W3;
    int i = (blockIdx.x & 63) * 256 + threadIdx.x;   // float4 index within weight
    float4 f = ((const float4*)W)[i];
    __half hx = __float2half(f.x), hy = __float2half(f.y);
    __half hz = __float2half(f.z), hw = __float2half(f.w);
    size_t off = (size_t)w * DD * DD + (size_t)i * 4;
    *(uint2*)(g_w_h + off) = make_uint2(hpack(hx, hy), hpack(hz, hw));
    *(uint2*)(g_w_l + off) = make_uint2(
        hpack(__float2half(f.x - __half2float(hx)), __float2half(f.y - __half2float(hy))),
        hpack(__float2half(f.z - __half2float(hz)), __float2half(f.w - __half2float(hw))));
}

// ================================================================
// Tensorized projection: C[2048,256] = A @ W^T + b.
// CTA 64x64, BK=32, 8 warps, f16 hi/lo 3-term. Epilogue mode:
//   0: q -> g_qh hi/lo scaled by QSCALE   1: k -> g_kh hi/lo
//   2: v -> transposed into g_vt hi/lo    3: fp32 -> Cout
// ================================================================
__global__ __launch_bounds__(256) void gemm_proj_mma(const float* __restrict__ A,
                                                     const __half* __restrict__ Wh,
                                                     const __half* __restrict__ Wl,
                                                     const float* __restrict__ bias,
                                                     float* __restrict__ Cout,
                                                     int mode) {
    __shared__ __align__(16) char sm[20480];
    __half* Ahi = (__half*)sm;              // [64][40]
    __half* Alo = (__half*)(sm + 5120);
    __half* Bhi = (__half*)(sm + 10240);
    __half* Blo = (__half*)(sm + 15360);
    float* stage = (float*)sm;              // overlay [64][68] = 17408 B

    int tid = threadIdx.x, wid = tid >> 5, lane = tid & 31;
    int m0 = blockIdx.x * 64, n0 = blockIdx.y * 64;
    int wm = (wid >> 2) * 32, wn = (wid & 3) * 16;
    int a_m = lane & 15, a_k = (lane >> 4) << 3;
    int b_n = (lane & 7) + ((lane >> 4) << 3);
    int b_k = ((lane >> 3) & 1) << 3;
    int lr = tid >> 2, lc8 = (tid & 3) * 8;

    const float* pa = A + (size_t)(m0 + lr) * DD + lc8;
    const __half* pbh = Wh + (size_t)(n0 + lr) * DD + lc8;
    const __half* pbl = Wl + (size_t)(n0 + lr) * DD + lc8;

    float acc[2][2][4] = {};

    // prefetch kb=0
    float4 f0 = *(const float4*)pa, f1 = *(const float4*)(pa + 4);
    int4 wbh = *(const int4*)pbh, wbl = *(const int4*)pbl;

    for (int kb = 0; kb < 8; kb++) {
        __syncthreads();
        {   // store A hi/lo + W tiles
            float v[8] = {f0.x, f0.y, f0.z, f0.w, f1.x, f1.y, f1.z, f1.w};
            int4 ph, pl;
            split8(v, ph, pl);
            *(int4*)&Ahi[lr * 40 + lc8] = ph;
            *(int4*)&Alo[lr * 40 + lc8] = pl;
            *(int4*)&Bhi[lr * 40 + lc8] = wbh;
            *(int4*)&Blo[lr * 40 + lc8] = wbl;
        }
        __syncthreads();
        if (kb < 7) {   // prefetch next
            int k0 = (kb + 1) * 32;
            f0 = *(const float4*)(pa + k0);
            f1 = *(const float4*)(pa + k0 + 4);
            wbh = *(const int4*)(pbh + k0);
            wbl = *(const int4*)(pbl + k0);
        }
#pragma unroll
        for (int ks = 0; ks < 2; ks++) {
            int kk = ks * 16;
            uint32_t ahi[2][4], alo[2][4], bhi[4], blo[4];
#pragma unroll
            for (int mt = 0; mt < 2; mt++) {
                LDSM4(ahi[mt], &Ahi[(wm + mt * 16 + a_m) * 40 + kk + a_k]);
                LDSM4(alo[mt], &Alo[(wm + mt * 16 + a_m) * 40 + kk + a_k]);
            }
            LDSM4(bhi, &Bhi[(wn + b_n) * 40 + kk + b_k]);
            LDSM4(blo, &Blo[(wn + b_n) * 40 + kk + b_k]);
#pragma unroll
            for (int mt = 0; mt < 2; mt++)
#pragma unroll
                for (int nt = 0; nt < 2; nt++) {
                    MMA_F16(acc[mt][nt], ahi[mt], bhi[nt * 2], bhi[nt * 2 + 1]);
                    MMA_F16(acc[mt][nt], alo[mt], bhi[nt * 2], bhi[nt * 2 + 1]);
                    MMA_F16(acc[mt][nt], ahi[mt], blo[nt * 2], blo[nt * 2 + 1]);
                }
        }
    }
    __syncthreads();

    // bias + scale, stage to smem (stride 68 floats = 272 B, float4-safe)
    int rbase = wm + (lane >> 2), cbase = wn + 2 * (lane & 3);
    float scl = (mode == 0) ? QSCALE : 1.0f;
#pragma unroll
    for (int nt = 0; nt < 2; nt++) {
        int c = cbase + nt * 8;
        float b0 = bias[n0 + c], b1 = bias[n0 + c + 1];
#pragma unroll
        for (int mt = 0; mt < 2; mt++) {
            int r = rbase + mt * 16;
            stage[r * 68 + c]           = (acc[mt][nt][0] + b0) * scl;
            stage[r * 68 + c + 1]       = (acc[mt][nt][1] + b1) * scl;
            stage[(r + 8) * 68 + c]     = (acc[mt][nt][2] + b0) * scl;
            stage[(r + 8) * 68 + c + 1] = (acc[mt][nt][3] + b1) * scl;
        }
    }
    __syncthreads();

    if (mode == 3) {
        int row = tid >> 2, c0 = (tid & 3) * 16;
#pragma unroll
        for (int e = 0; e < 4; e++) {
            float4 o = *(float4*)&stage[row * 68 + c0 + e * 4];
            *(float4*)(Cout + (size_t)(m0 + row) * DD + n0 + c0 + e * 4) = o;
        }
        return;
    }

    if (mode == 2) {
        int dl = tid >> 2, ml0 = (tid & 3) * 16;
        float v[16];
#pragma unroll
        for (int e = 0; e < 16; e++) v[e] = stage[(ml0 + e) * 68 + dl];
        size_t off = (size_t)(n0 + dl) * NN + m0 + ml0;
#pragma unroll
        for (int c = 0; c < 2; c++) {
            int4 ph, pl;
            split8(v + c * 8, ph, pl);
            *(int4*)(g_vt_h + off + c * 8) = ph;
            *(int4*)(g_vt_l + off + c * 8) = pl;
        }
        return;
    }

    // mode 0/1
    __half* Hh = (mode == 0) ? g_qh_h : g_kh_h;
    __half* Hl = (mode == 0) ? g_qh_l : g_kh_l;
    int row = tid >> 2, c0 = (tid & 3) * 16;
    float v[16];
#pragma unroll
    for (int e = 0; e < 16; e++) v[e] = stage[row * 68 + c0 + e];
    size_t off = (size_t)(m0 + row) * DD + n0 + c0;
#pragma unroll
    for (int c = 0; c < 2; c++) {
        int4 ph, pl;
        split8(v + c * 8, ph, pl);
        *(int4*)(Hh + off + c * 8) = ph;
        *(int4*)(Hl + off + c * 8) = pl;
    }
}

// ================================================================
// Flash attention via mma.sync. CTA = (128 rows, 1 head), 512 thr / 16 warps.
// Warp-group wg (0/1) handles key n-tiles 4wg..4wg+3; warp wr owns rows
// 16wr..16wr+15. Register-prefetch of next K/V tile overlaps gmem latency
// with MMA compute. Partial (o,l) additive -> smem merge.
// ================================================================
__global__ __launch_bounds__(512) void attn_mma(const float* __restrict__ mask) {
    __shared__ __align__(16) char sm[44544];
    __half* Qh = (__half*)sm;               // [128][40]
    __half* Ql = (__half*)(sm + 10240);
    __half* Kh = (__half*)(sm + 20480);     // [64][40]
    __half* Kl = (__half*)(sm + 25600);
    __half* Vh = (__half*)(sm + 30720);     // [48][72]
    __half* Vl = (__half*)(sm + 37632);
    float* stage = (float*)(sm + 20480);    // overlay: [8*32][21] floats

    int tid = threadIdx.x, warp = tid >> 5, lane = tid & 31;
    int wg = warp >> 3, wr = warp & 7;
    int h = blockIdx.y, r0 = blockIdx.x * 128;

    {   // Q tile (128x32) hi/lo
        int row = tid >> 2, seg = tid & 3;
        *(int4*)&Qh[row * 40 + seg * 8] = *(const int4*)(g_qh_h + (size_t)(r0 + row) * DD + h * 32 + seg * 8);
        *(int4*)&Ql[row * 40 + seg * 8] = *(const int4*)(g_qh_l + (size_t)(r0 + row) * DD + h * 32 + seg * 8);
    }
    // V static rows 32..47: row 32 = ones (l accumulator), rest zero
    for (int i = tid; i < 16 * 72; i += 512) {
        int r = 32 + i / 72, c = i % 72;
        Vh[r * 72 + c] = (r == 32) ? __float2half(1.0f) : __ushort_as_half(0);
        Vl[r * 72 + c] = __ushort_as_half(0);
    }
    __syncthreads();

    uint32_t qf_h[2][4], qf_l[2][4];
    int a_m = lane & 15, a_k = (lane >> 4) << 3;
#pragma unroll
    for (int ks = 0; ks < 2; ks++) {
        LDSM4(qf_h[ks], &Qh[(wr * 16 + a_m) * 40 + ks * 16 + a_k]);
        LDSM4(qf_l[ks], &Ql[(wr * 16 + a_m) * 40 + ks * 16 + a_k]);
    }

    // per-thread K/V streaming pointers + smem store targets
    const __half *src_h, *src_l;
    __half *dst_h, *dst_l;
    size_t step;
    if (tid < 256) {
        int row = tid >> 2, seg = tid & 3;
        src_h = g_kh_h + (size_t)row * DD + h * 32 + seg * 8;
        src_l = g_kh_l + (size_t)row * DD + h * 32 + seg * 8;
        dst_h = &Kh[row * 40 + seg * 8];
        dst_l = &Kl[row * 40 + seg * 8];
        step = (size_t)64 * DD;
    } else {
        int t = tid - 256, row = t >> 3, seg = t & 7;
        src_h = g_vt_h + (size_t)(h * 32 + row) * NN + seg * 8;
        src_l = g_vt_l + (size_t)(h * 32 + row) * NN + seg * 8;
        dst_h = &Vh[row * 72 + seg * 8];
        dst_l = &Vl[row * 72 + seg * 8];
        step = 64;
    }

    int b_n = (lane & 7) + ((lane >> 4) << 3);
    int b_k = ((lane >> 3) & 1) << 3;
    int mrow = r0 + wr * 16 + (lane >> 2);
    int mcol = 2 * (lane & 3);

    float o[5][4] = {};

    // prefetch tile 0
    int4 tph = *(const int4*)src_h, tpl = *(const int4*)src_l;

    for (int kt = 0; kt < 32; kt++) {
        int k0 = kt * 64;
        __syncthreads();
        *(int4*)dst_h = tph;
        *(int4*)dst_l = tpl;
        __syncthreads();
        if (kt < 31) {   // prefetch next tile — overlaps with compute below
            tph = *(const int4*)(src_h + (size_t)(kt + 1) * step);
            tpl = *(const int4*)(src_l + (size_t)(kt + 1) * step);
        }

        // ---- scores: this wg's 4 n-tiles (2 key-groups of 16) ----
        float sc[4][4] = {};
#pragma unroll
        for (int ks = 0; ks < 2; ks++)
#pragma unroll
            for (int gl = 0; gl < 2; gl++) {
                int g = 2 * wg + gl;
                uint32_t bh[4], bl[4];
                LDSM4(bh, &Kh[(g * 16 + b_n) * 40 + ks * 16 + b_k]);
                LDSM4(bl, &Kl[(g * 16 + b_n) * 40 + ks * 16 + b_k]);
                MMA_F16(sc[2 * gl],     qf_h[ks], bh[0], bh[1]);
                MMA_F16(sc[2 * gl],     qf_l[ks], bh[0], bh[1]);
                MMA_F16(sc[2 * gl],     qf_h[ks], bl[0], bl[1]);
                MMA_F16(sc[2 * gl + 1], qf_h[ks], bh[2], bh[3]);
                MMA_F16(sc[2 * gl + 1], qf_l[ks], bh[2], bh[3]);
                MMA_F16(sc[2 * gl + 1], qf_h[ks], bl[2], bl[3]);
            }

        // ---- + mask*log2e, exp2, pack P ----
        uint32_t P[2][4];
#pragma unroll
        for (int ntl = 0; ntl < 4; ntl++) {
            int nt = 4 * wg + ntl;
            const float2 mA = *(const float2*)(mask + (size_t)mrow * NN + k0 + nt * 8 + mcol);
            const float2 mB = *(const float2*)(mask + (size_t)(mrow + 8) * NN + k0 + nt * 8 + mcol);
            sc[ntl][0] = fmaf(mA.x, LOG2E, sc[ntl][0]);
            sc[ntl][1] = fmaf(mA.y, LOG2E, sc[ntl][1]);
            sc[ntl][2] = fmaf(mB.x, LOG2E, sc[ntl][2]);
            sc[ntl][3] = fmaf(mB.y, LOG2E, sc[ntl][3]);
            uint32_t e01, e23;
            CVT_F16X2(e01, sc[ntl][1], sc[ntl][0]);
            CVT_F16X2(e23, sc[ntl][3], sc[ntl][2]);
            EX2_F16X2(e01);
            EX2_F16X2(e23);
            P[ntl >> 1][(ntl & 1) * 2]     = e01;
            P[ntl >> 1][(ntl & 1) * 2 + 1] = e23;
        }

        // ---- PV over this wg's 2 key-groups ----
#pragma unroll
        for (int gl = 0; gl < 2; gl++) {
            int g = 2 * wg + gl;
            uint32_t v0h[4], v1h[4], v2h[4], v0l[4], v1l[4];
            LDSM4(v0h, &Vh[b_n * 72 + g * 16 + b_k]);
            LDSM4(v1h, &Vh[(16 + b_n) * 72 + g * 16 + b_k]);
            LDSM4(v2h, &Vh[(32 + b_n) * 72 + g * 16 + b_k]);
            LDSM4(v0l, &Vl[b_n * 72 + g * 16 + b_k]);
            LDSM4(v1l, &Vl[(16 + b_n) * 72 + g * 16 + b_k]);
            MMA_F16(o[0], P[gl], v0h[0], v0h[1]);
            MMA_F16(o[1], P[gl], v0h[2], v0h[3]);
            MMA_F16(o[2], P[gl], v1h[0], v1h[1]);
            MMA_F16(o[3], P[gl], v1h[2], v1h[3]);
            MMA_F16(o[4], P[gl], v2h[0], v2h[1]);   // l tile (col 32 = ones)
            MMA_F16(o[0], P[gl], v0l[0], v0l[1]);
            MMA_F16(o[1], P[gl], v0l[2], v0l[3]);
            MMA_F16(o[2], P[gl], v1l[0], v1l[1]);
            MMA_F16(o[3], P[gl], v1l[2], v1l[3]);
        }
    }

    // ---- merge wg1 partials into wg0, then write ----
    __syncthreads();
    if (wg == 1) {
        float* s = stage + (wr * 32 + lane) * 21;
#pragma unroll
        for (int i = 0; i < 5; i++)
#pragma unroll
            for (int j = 0; j < 4; j++) s[i * 4 + j] = o[i][j];
    }
    __syncthreads();
    if (wg == 0) {
        float* s = stage + (wr * 32 + lane) * 21;
#pragma unroll
        for (int i = 0; i < 5; i++)
#pragma unroll
            for (int j = 0; j < 4; j++) o[i][j] += s[i * 4 + j];

        float lr0 = __shfl_sync(0xffffffffu, o[4][0], lane & 28);
        float lr1 = __shfl_sync(0xffffffffu, o[4][2], lane & 28);
        float s0 = 0.5f / lr0, s1 = 0.5f / lr1;
        int orow = r0 + wr * 16 + (lane >> 2);
        int ocol = h * 32 + 2 * (lane & 3);
#pragma unroll
        for (int nt = 0; nt < 4; nt++) {
            *(float2*)(g_x + (size_t)orow * DD + ocol + nt * 8) =
                make_float2(o[nt][0] * s0, o[nt][1] * s0);
            *(float2*)(g_x + (size_t)(orow + 8) * DD + ocol + nt * 8) =
                make_float2(o[nt][2] * s1, o[nt][3] * s1);
        }
    }
}

// ================================================================
// Adjacency row sums -> g_inv[n] = 0.5 / (sum + 1e-6)  (pure reduction)
// ================================================================
__global__ __launch_bounds__(256) void rowsum_kernel(const float* __restrict__ adj) {
    int row = blockIdx.x;
    const float4* r4 = (const float4*)(adj + (size_t)row * NN);
    float s = 0.f;
    for (int i = threadIdx.x; i < NN / 4; i += 256) {
        float4 t = r4[i];
        s += t.x + t.y + t.z + t.w;
    }
#pragma unroll
    for (int o = 16; o > 0; o >>= 1) s += __shfl_xor_sync(0xffffffffu, s, o);
    __shared__ float red[8];
    if ((threadIdx.x & 31) == 0) red[threadIdx.x >> 5] = s;
    __syncthreads();
    if (threadIdx.x < 8) {
        float t = red[threadIdx.x];
#pragma unroll
        for (int o = 4; o > 0; o >>= 1) t += __shfl_xor_sync(0xffu, t, o);
        if (threadIdx.x == 0) g_inv[row] = 0.5f / (t + 1e-6f);
    }
}

// ================================================================
// Adjacency GEMM (mma.sync f16 hi/lo, inline fp32->hi/lo convert):
// g_x[m,n] += g_inv[m] * sum_k adj[m,k] * V[k,n]
// CTA 64x64, BK=32, 256 thr / 8 warps, register-prefetch. grid (32, 4).
// ================================================================
__global__ __launch_bounds__(256) void gemm_adj_mma(const float* __restrict__ adj) {
    __shared__ __align__(16) __half Ahi[64][40], Alo[64][40];
    __shared__ __align__(16) __half Bhi[64][40], Blo[64][40];

    int tid = threadIdx.x;
    int wid = tid >> 5, lane = tid & 31;
    int m0 = blockIdx.x * 64, n0 = blockIdx.y * 64;
    int wm = (wid >> 2) * 32;
    int wn = (wid & 3) * 16;

    int a_m = lane & 15, a_k = (lane >> 4) << 3;
    int b_n = (lane & 7) + ((lane >> 4) << 3);
    int b_k = ((lane >> 3) & 1) << 3;
    int lr = tid >> 2, lc = (tid & 3) * 8;

    const float* pa = adj + (size_t)(m0 + lr) * NN + lc;
    const __half* pbh = g_vt_h + (size_t)(n0 + lr) * NN + lc;
    const __half* pbl = g_vt_l + (size_t)(n0 + lr) * NN + lc;

    float acc[2][2][4] = {};

    // prefetch kb=0
    float4 f0 = *(const float4*)pa, f1 = *(const float4*)(pa + 4);
    int4 vbh = *(const int4*)pbh, vbl = *(const int4*)pbl;

    for (int kb = 0; kb < NN / 32; kb++) {
        __syncthreads();
        {
            float v[8] = {f0.x, f0.y, f0.z, f0.w, f1.x, f1.y, f1.z, f1.w};
            int4 ph, pl;
            split8(v, ph, pl);
            *(int4*)&Ahi[lr][lc] = ph;
            *(int4*)&Alo[lr][lc] = pl;
            *(int4*)&Bhi[lr][lc] = vbh;
            *(int4*)&Blo[lr][lc] = vbl;
        }
        __syncthreads();
        if (kb < NN / 32 - 1) {
            int k0 = (kb + 1) * 32;
            f0 = *(const float4*)(pa + k0);
            f1 = *(const float4*)(pa + k0 + 4);
            vbh = *(const int4*)(pbh + k0);
            vbl = *(const int4*)(pbl + k0);
        }

#pragma unroll
        for (int ks = 0; ks < 2; ks++) {
            int kk = ks * 16;
            uint32_t ahi[2][4], alo[2][4], bhi[4], blo[4];
#pragma unroll
            for (int mt = 0; mt < 2; mt++) {
                LDSM4(ahi[mt], &Ahi[wm + mt * 16 + a_m][kk + a_k]);
                LDSM4(alo[mt], &Alo[wm + mt * 16 + a_m][kk + a_k]);
            }
            LDSM4(bhi, &Bhi[wn + b_n][kk + b_k]);
            LDSM4(blo, &Blo[wn + b_n][kk + b_k]);

#pragma unroll
            for (int mt = 0; mt < 2; mt++)
#pragma unroll
                for (int nt = 0; nt < 2; nt++) {
                    MMA_F16(acc[mt][nt], ahi[mt], bhi[nt * 2], bhi[nt * 2 + 1]);
                    MMA_F16(acc[mt][nt], alo[mt], bhi[nt * 2], bhi[nt * 2 + 1]);
                    MMA_F16(acc[mt][nt], ahi[mt], blo[nt * 2], blo[nt * 2 + 1]);
                }
        }
    }

    int rbase = wm + (lane >> 2);
    int cbase = wn + 2 * (lane & 3);
#pragma unroll
    for (int mt = 0; mt < 2; mt++) {
        int r = m0 + rbase + mt * 16;
        float rs0 = g_inv[r], rs1 = g_inv[r + 8];
#pragma unroll
        for (int nt = 0; nt < 2; nt++) {
            int c = n0 + cbase + nt * 8;
            float2 p0 = *(float2*)(g_x + (size_t)r * DD + c);
            float2 p1 = *(float2*)(g_x + (size_t)(r + 8) * DD + c);
            p0.x += acc[mt][nt][0] * rs0; p0.y += acc[mt][nt][1] * rs0;
            p1.x += acc[mt][nt][2] * rs1; p1.y += acc[mt][nt][3] * rs1;
            *(float2*)(g_x + (size_t)r * DD + c) = p0;
            *(float2*)(g_x + (size_t)(r + 8) * DD + c) = p1;
        }
    }
}

// ================================================================
extern "C" void kernel_launch(void* const* d_in, const int* in_sizes, int n_in,
                              void* d_out, int out_size) {
    const float* query = (const float*)d_in[0];
    const float* key   = (const float*)d_in[1];
    const float* value = (const float*)d_in[2];
    const float* mask  = (const float*)d_in[3];
    const float* adj   = (const float*)d_in[4];
    const float* Wq = (const float*)d_in[5];  const float* bq = (const float*)d_in[6];
    const float* Wk = (const float*)d_in[7];  const float* bk = (const float*)d_in[8];
    const float* Wv = (const float*)d_in[9];  const float* bv = (const float*)d_in[10];
    const float* Wo = (const float*)d_in[11]; const float* bo = (const float*)d_in[12];
    float* out = (float*)d_out;

    float* px;
    __half *pwh, *pwl;
    cudaGetSymbolAddress((void**)&px, g_x);
    cudaGetSymbolAddress((void**)&pwh, g_w_h);
    cudaGetSymbolAddress((void**)&pwl, g_w_l);

    const int WSZ = DD * DD;

    // 0: fused weight splits
    wconvert4<<<256, 256>>>(Wq, Wk, Wv, Wo);

    dim3 pgrid(NN / 64, DD / 64);

    // 1-3: tensorized projections with fused f16 hi/lo epilogues
    gemm_proj_mma<<<pgrid, 256>>>(query, pwh + 0 * WSZ, pwl + 0 * WSZ, bq, nullptr, 0);
    gemm_proj_mma<<<pgrid, 256>>>(key,   pwh + 1 * WSZ, pwl + 1 * WSZ, bk, nullptr, 1);
    gemm_proj_mma<<<pgrid, 256>>>(value, pwh + 2 * WSZ, pwl + 2 * WSZ, bv, nullptr, 2);

    // 4: tensor-core flash attention -> g_x = 0.5*attn
    attn_mma<<<dim3(NN / 128, HH), 512>>>(mask);

    // 5: adjacency row sums (pure)
    rowsum_kernel<<<NN, 256>>>(adj);

    // 6: g_x += 0.5 * p_adj @ V (tensor cores, inline adj convert)
    gemm_adj_mma<<<dim3(NN / 64, DD / 64), 256>>>(adj);

    // 7: output projection (fp32 out)
    gemm_proj_mma<<<pgrid, 256>>>(px, pwh + 3 * WSZ, pwl + 3 * WSZ, bo, out, 3);
}